// round 14
// baseline (speedup 1.0000x reference)
#include <cuda_runtime.h>
#include <cuda_bf16.h>
#include <cstdint>

// ---------------------------------------------------------------------------
// MultiHead2DAttention (Shaw relative positions, T2T variant)
// B=2, L=1024, D=1024, H=16, DH=64, M=64, R=129
// Round 13: mega_attn_kernel goes 256 -> 512 threads (16 warps/SM instead of
// 8; smem layout unchanged at ~188KB, 1 CTA/SM). Budget analysis showed mega
// at ~480us (dominant), running at ~50% of its FFMA2 roof purely from low
// occupancy. GEMMs and other kernels unchanged from passing R12 (776us).
// ---------------------------------------------------------------------------

namespace {
constexpr int B  = 2;
constexpr int L  = 1024;
constexpr int D  = 1024;
constexpr int H  = 16;
constexpr int DH = 64;
constexpr int MREL = 64;
constexpr int R  = 2 * MREL + 1;   // 129
constexpr int RP = 132;            // padded row stride for relq
constexpr int NT = B * L;          // 2048
constexpr int BH = B * H;          // 32
constexpr int KST = 132;           // K-stage stride (phase 1, float2/4 access)
constexpr int VST = 130;           // V-stage stride (phase 3/4, u64 access)
constexpr int QKV = 3 * D;         // 3072: row stride of fused qkv buffer
}

typedef __nv_bfloat16 bf16;
typedef unsigned long long u64;
typedef unsigned int u32;

// Scratch buffers (device globals: no allocations allowed)
__device__ float g_qkv[(size_t)NT * QKV];   // fused q|k|v, row stride 3072
__device__ float g_o[NT * D];
__device__ float g_relq[(size_t)BH * L * RP];

// bf16 split buffers
__device__ bf16 g_xh[NT * D];
__device__ bf16 g_xl[NT * D];
__device__ bf16 g_wh3[(size_t)3 * D * D];   // Wq|Wk|Wv transposed [3N][K]
__device__ bf16 g_wl3[(size_t)3 * D * D];
__device__ bf16 g_woh[D * D];               // Wo transposed [N][K]
__device__ bf16 g_wol[D * D];

// ---------------------------------------------------------------------------
// packed fp32 helpers
// ---------------------------------------------------------------------------
__device__ __forceinline__ u64 pk2(float x, float y) {
    u64 r;
    asm("mov.b64 %0, {%1, %2};" : "=l"(r) : "f"(x), "f"(y));
    return r;
}
__device__ __forceinline__ u64 dup2(float x) { return pk2(x, x); }
__device__ __forceinline__ u64 ffma2(u64 a, u64 b, u64 c) {
    u64 d;
    asm("fma.rn.f32x2 %0, %1, %2, %3;" : "=l"(d) : "l"(a), "l"(b), "l"(c));
    return d;
}
__device__ __forceinline__ float2 up2(u64 v) {
    float2 f;
    asm("mov.b64 {%0, %1}, %2;" : "=f"(f.x), "=f"(f.y) : "l"(v));
    return f;
}

// ---------------------------------------------------------------------------
// mma helper: D(f32) += A(bf16 16x16) * B(bf16 16x8)
// ---------------------------------------------------------------------------
__device__ __forceinline__ void mma16816(float* c, const u32* a, const u32* b) {
    asm volatile(
        "mma.sync.aligned.m16n8k16.row.col.f32.bf16.bf16.f32 "
        "{%0,%1,%2,%3},{%4,%5,%6,%7},{%8,%9},{%0,%1,%2,%3};"
        : "+f"(c[0]), "+f"(c[1]), "+f"(c[2]), "+f"(c[3])
        : "r"(a[0]), "r"(a[1]), "r"(a[2]), "r"(a[3]), "r"(b[0]), "r"(b[1]));
}

__device__ __forceinline__ void cp16(u32 smem_addr, const void* gptr) {
    asm volatile("cp.async.cg.shared.global [%0], [%1], 16;"
                 :: "r"(smem_addr), "l"(gptr));
}

// ---------------------------------------------------------------------------
// split: src fp32 -> hi/lo bf16 (elementwise)
// ---------------------------------------------------------------------------
__global__ __launch_bounds__(256) void split_kernel(const float* __restrict__ src,
                                                    bf16* __restrict__ hi,
                                                    bf16* __restrict__ lo) {
    int i = (blockIdx.x * 256 + threadIdx.x) * 4;
    float4 v = *(const float4*)(src + i);
    bf16 h0 = __float2bfloat16(v.x);
    bf16 h1 = __float2bfloat16(v.y);
    bf16 h2 = __float2bfloat16(v.z);
    bf16 h3 = __float2bfloat16(v.w);
    bf16 l0 = __float2bfloat16(v.x - __bfloat162float(h0));
    bf16 l1 = __float2bfloat16(v.y - __bfloat162float(h1));
    bf16 l2 = __float2bfloat16(v.z - __bfloat162float(h2));
    bf16 l3 = __float2bfloat16(v.w - __bfloat162float(h3));
    __nv_bfloat162* hp = (__nv_bfloat162*)(hi + i);
    __nv_bfloat162* lp = (__nv_bfloat162*)(lo + i);
    hp[0] = __nv_bfloat162(h0, h1);
    hp[1] = __nv_bfloat162(h2, h3);
    lp[0] = __nv_bfloat162(l0, l1);
    lp[1] = __nv_bfloat162(l2, l3);
}

// ---------------------------------------------------------------------------
// splitT3: three W[K][N] fp32 -> transposed hi/lo bf16 stacked [3N][K]
// ---------------------------------------------------------------------------
__global__ void splitT3_kernel(const float* __restrict__ W0,
                               const float* __restrict__ W1,
                               const float* __restrict__ W2,
                               bf16* __restrict__ th, bf16* __restrict__ tl) {
    __shared__ float ts[32][33];
    const int tx = threadIdx.x, ty = threadIdx.y;
    const int n0 = blockIdx.x * 32, k0 = blockIdx.y * 32;
    const int z = blockIdx.z;
    const float* W = (z == 0) ? W0 : (z == 1) ? W1 : W2;
    for (int r = ty; r < 32; r += 8)
        ts[r][tx] = W[(size_t)(k0 + r) * D + n0 + tx];
    __syncthreads();
    const size_t zofs = (size_t)z * D * D;
    for (int r = ty; r < 32; r += 8) {
        float v = ts[tx][r];
        bf16 h = __float2bfloat16(v);
        bf16 l = __float2bfloat16(v - __bfloat162float(h));
        th[zofs + (size_t)(n0 + r) * D + k0 + tx] = h;
        tl[zofs + (size_t)(n0 + r) * D + k0 + tx] = l;
    }
}

// single-weight variant (Wo)
__global__ void splitT_kernel(const float* __restrict__ W,
                              bf16* __restrict__ th, bf16* __restrict__ tl) {
    __shared__ float ts[32][33];
    const int tx = threadIdx.x, ty = threadIdx.y;
    const int n0 = blockIdx.x * 32, k0 = blockIdx.y * 32;
    for (int r = ty; r < 32; r += 8)
        ts[r][tx] = W[(size_t)(k0 + r) * D + n0 + tx];
    __syncthreads();
    for (int r = ty; r < 32; r += 8) {
        float v = ts[tx][r];
        bf16 h = __float2bfloat16(v);
        bf16 l = __float2bfloat16(v - __bfloat162float(h));
        th[(size_t)(n0 + r) * D + k0 + tx] = h;
        tl[(size_t)(n0 + r) * D + k0 + tx] = l;
    }
}

// ---------------------------------------------------------------------------
// hgemm3x: unchanged from R12 (3-stage cp.async ring)
// ---------------------------------------------------------------------------
namespace {
constexpr int HG_STR = 24;
constexpr u32 HG_TB = 128 * HG_STR * 2;
constexpr u32 HG_STAGE_B = 4 * HG_TB;
constexpr u32 HG_SMEM = 3 * HG_STAGE_B;
}

__global__ __launch_bounds__(256) void hgemm3x(const bf16* __restrict__ Ah,
                                               const bf16* __restrict__ Al,
                                               const bf16* __restrict__ Bh,
                                               const bf16* __restrict__ Bl,
                                               float* __restrict__ C,
                                               int Md, int Nd, int Kd) {
    extern __shared__ __align__(16) bf16 hsm[];
    const u32 sbase = (u32)__cvta_generic_to_shared(hsm);

    const int tid = threadIdx.x;
    const int bm = blockIdx.y * 128;
    const int bn = blockIdx.x * 128;
    const int wid = tid >> 5;
    const int lane = tid & 31;
    const int g = lane >> 2;
    const int tg = lane & 3;
    const int wm = (wid & 1) * 64;
    const int wn = (wid >> 1) * 32;

    const int lrow = tid >> 1;
    const int lseg = (tid & 1) * 8;
    const size_t aoff = (size_t)(bm + lrow) * Kd + lseg;
    const size_t boff = (size_t)(bn + lrow) * Kd + lseg;
    const u32 sdst = (u32)(lrow * HG_STR + lseg) * 2;

    float acc[4][4][4];
#pragma unroll
    for (int ma = 0; ma < 4; ++ma)
#pragma unroll
        for (int na = 0; na < 4; ++na)
#pragma unroll
            for (int e = 0; e < 4; ++e) acc[ma][na][e] = 0.0f;

    const int nT = Kd / 16;

    auto stage_tile = [&](int kt, int slot) {
        const u32 o = sbase + (u32)slot * HG_STAGE_B + sdst;
        const size_t ko = (size_t)kt * 16;
        cp16(o + 0 * HG_TB, Ah + aoff + ko);
        cp16(o + 1 * HG_TB, Al + aoff + ko);
        cp16(o + 2 * HG_TB, Bh + boff + ko);
        cp16(o + 3 * HG_TB, Bl + boff + ko);
        asm volatile("cp.async.commit_group;");
    };

    stage_tile(0, 0);
    if (nT > 1) stage_tile(1, 1);

    int slot = 0;
    for (int kt = 0; kt < nT; ++kt) {
        if (kt + 1 < nT) {
            asm volatile("cp.async.wait_group 1;" ::: "memory");
        } else {
            asm volatile("cp.async.wait_group 0;" ::: "memory");
        }
        __syncthreads();
        if (kt + 2 < nT) stage_tile(kt + 2, (slot + 2) % 3);

        const bf16* Abh = hsm + (size_t)slot * (HG_STAGE_B / 2);
        const bf16* Abl = Abh + HG_TB / 2;
        const bf16* Bbh = Abh + 2 * (HG_TB / 2);
        const bf16* Bbl = Abh + 3 * (HG_TB / 2);

        u32 ah[4][4], al[4][4], bh[4][2], bl[4][2];
#pragma unroll
        for (int ma = 0; ma < 4; ++ma) {
            const int r0 = (wm + ma * 16 + g) * HG_STR + 2 * tg;
            const int r1 = r0 + 8 * HG_STR;
            ah[ma][0] = *(const u32*)(Abh + r0);
            ah[ma][1] = *(const u32*)(Abh + r1);
            ah[ma][2] = *(const u32*)(Abh + r0 + 8);
            ah[ma][3] = *(const u32*)(Abh + r1 + 8);
            al[ma][0] = *(const u32*)(Abl + r0);
            al[ma][1] = *(const u32*)(Abl + r1);
            al[ma][2] = *(const u32*)(Abl + r0 + 8);
            al[ma][3] = *(const u32*)(Abl + r1 + 8);
        }
#pragma unroll
        for (int na = 0; na < 4; ++na) {
            const int c0 = (wn + na * 8 + g) * HG_STR + 2 * tg;
            bh[na][0] = *(const u32*)(Bbh + c0);
            bh[na][1] = *(const u32*)(Bbh + c0 + 8);
            bl[na][0] = *(const u32*)(Bbl + c0);
            bl[na][1] = *(const u32*)(Bbl + c0 + 8);
        }

#pragma unroll
        for (int ma = 0; ma < 4; ++ma)
#pragma unroll
            for (int na = 0; na < 4; ++na)
                mma16816(acc[ma][na], ah[ma], bh[na]);
#pragma unroll
        for (int ma = 0; ma < 4; ++ma)
#pragma unroll
            for (int na = 0; na < 4; ++na)
                mma16816(acc[ma][na], ah[ma], bl[na]);
#pragma unroll
        for (int ma = 0; ma < 4; ++ma)
#pragma unroll
            for (int na = 0; na < 4; ++na)
                mma16816(acc[ma][na], al[ma], bh[na]);

        slot = (slot + 1) % 3;
    }

#pragma unroll
    for (int ma = 0; ma < 4; ++ma) {
#pragma unroll
        for (int na = 0; na < 4; ++na) {
            const int r0 = bm + wm + ma * 16 + g;
            const int c = bn + wn + na * 8 + 2 * tg;
            *(float2*)(C + (size_t)r0 * Nd + c) =
                make_float2(acc[ma][na][0], acc[ma][na][1]);
            *(float2*)(C + (size_t)(r0 + 8) * Nd + c) =
                make_float2(acc[ma][na][2], acc[ma][na][3]);
        }
    }
}

// ---------------------------------------------------------------------------
// relq[bh,i,r] = (q_scaled)[bh,i,:] . rel_k_table[r,:]   (unchanged)
// ---------------------------------------------------------------------------
__global__ __launch_bounds__(256) void relq_kernel(const float* __restrict__ relk) {
    __shared__ __align__(16) float qsT[64][36];
    __shared__ __align__(16) float tsT[64][132];

    const int tid = threadIdx.x;
    const int bh = blockIdx.y;
    const int b = bh >> 4;
    const int h = bh & 15;
    const int i0 = blockIdx.x * 32;
    const int tx = tid & 31;
    const int ty = tid >> 5;
    const float QS = 0.125f;

    {
        const int rI = tid >> 3;
        const int seg = (tid & 7) * 8;
        const float* qb = g_qkv + (size_t)(b * L + i0 + rI) * QKV + h * DH + seg;
        float4 v0 = *(const float4*)qb;
        float4 v1 = *(const float4*)(qb + 4);
        qsT[seg + 0][rI] = v0.x * QS; qsT[seg + 1][rI] = v0.y * QS;
        qsT[seg + 2][rI] = v0.z * QS; qsT[seg + 3][rI] = v0.w * QS;
        qsT[seg + 4][rI] = v1.x * QS; qsT[seg + 5][rI] = v1.y * QS;
        qsT[seg + 6][rI] = v1.z * QS; qsT[seg + 7][rI] = v1.w * QS;
    }
    for (int e = tid; e < R * 64; e += 256) {
        int r = e >> 6, d = e & 63;
        tsT[d][r] = relk[e];
    }
    __syncthreads();

    u64 acc2[2][4];
#pragma unroll
    for (int p = 0; p < 2; ++p)
#pragma unroll
        for (int j = 0; j < 4; ++j) acc2[p][j] = 0ull;

#pragma unroll 8
    for (int d = 0; d < 64; ++d) {
        const u64* ap = (const u64*)&qsT[d][ty * 4];
        u64 pa0 = ap[0], pa1 = ap[1];
        float4 bv = *(const float4*)&tsT[d][tx * 4];
        u64 pb0 = dup2(bv.x), pb1 = dup2(bv.y), pb2 = dup2(bv.z), pb3 = dup2(bv.w);
        acc2[0][0] = ffma2(pa0, pb0, acc2[0][0]);
        acc2[0][1] = ffma2(pa0, pb1, acc2[0][1]);
        acc2[0][2] = ffma2(pa0, pb2, acc2[0][2]);
        acc2[0][3] = ffma2(pa0, pb3, acc2[0][3]);
        acc2[1][0] = ffma2(pa1, pb0, acc2[1][0]);
        acc2[1][1] = ffma2(pa1, pb1, acc2[1][1]);
        acc2[1][2] = ffma2(pa1, pb2, acc2[1][2]);
        acc2[1][3] = ffma2(pa1, pb3, acc2[1][3]);
    }

#pragma unroll
    for (int p = 0; p < 2; ++p) {
        float2 c0 = up2(acc2[p][0]);
        float2 c1 = up2(acc2[p][1]);
        float2 c2 = up2(acc2[p][2]);
        float2 c3 = up2(acc2[p][3]);
        int gi = i0 + ty * 4 + 2 * p;
        float* o0 = g_relq + ((size_t)bh * L + gi) * RP + tx * 4;
        float* o1 = o0 + RP;
        *(float4*)o0 = make_float4(c0.x, c1.x, c2.x, c3.x);
        *(float4*)o1 = make_float4(c0.y, c1.y, c2.y, c3.y);
    }

    if (tid < 32) {
        float s = 0.0f;
#pragma unroll 8
        for (int d = 0; d < 64; ++d) s += qsT[d][tid] * tsT[d][128];
        g_relq[((size_t)bh * L + i0 + tid) * RP + 128] = s;
    }
}

// ---------------------------------------------------------------------------
// MEGA-fused attention, 512 threads (16 warps). Same math & smem as R12.
//   Phase 1: thread = 4i x 2j (ty=tid>>6, txx=tid&63)
//   Phase 2: 16 lanes per row
//   Phase 3/4: thread = 4i x 1d (d = txx)
// ---------------------------------------------------------------------------
namespace {
constexpr int SBS = 1032;  // Sb row stride (floats)
constexpr u32 FUSED_SMEM_FLOATS = 32 * SBS       // Sb
                                  + 64 * KST     // KV
                                  + 64 * 36      // QsT
                                  + 32 * 132     // biasW
                                  + 32;          // invS
constexpr u32 FUSED_SMEM = FUSED_SMEM_FLOATS * 4;
}

__global__ __launch_bounds__(512, 1) void mega_attn_kernel(
        const float* __restrict__ relv) {
    extern __shared__ float fs[];
    float* Sb    = fs;                       // [32][SBS]
    float* KV    = Sb + 32 * SBS;            // [64][KST] (K) / [64][VST] (V)
    float* QsT   = KV + 64 * KST;            // [64][36]
    float* biasW = QsT + 64 * 36;            // [32][132]
    float* invS  = biasW + 32 * 132;         // [32]

    const int tid = threadIdx.x;
    const int bh = blockIdx.y;
    const int b = bh >> 4;
    const int h = bh & 15;
    const int i0 = blockIdx.x * 32;
    const float QS = 0.125f;

    // ---- stage QsT (scaled): 512 threads, 1 float4 each ----
    {
        const int rI = tid >> 4;            // 0..31
        const int seg = (tid & 15) * 4;     // 0..60
        const float* qb = g_qkv + (size_t)(b * L + i0 + rI) * QKV + h * DH + seg;
        float4 v = *(const float4*)qb;
        QsT[(seg + 0) * 36 + rI] = v.x * QS;
        QsT[(seg + 1) * 36 + rI] = v.y * QS;
        QsT[(seg + 2) * 36 + rI] = v.z * QS;
        QsT[(seg + 3) * 36 + rI] = v.w * QS;
    }
    // ---- stage bias rows ----
    for (int e = tid; e < 32 * 132; e += 512) {
        int il = e / 132, r = e - il * 132;
        biasW[e] = (r < R) ? g_relq[((size_t)bh * L + i0 + il) * RP + r] : 0.0f;
    }

    const int ty = tid >> 6;            // 0..7  -> 4 i rows each
    const int txx = tid & 63;           // 0..63
    const int rJ = tid >> 2;            // 0..127 (staging row within chunk)
    const int segk = (tid & 3) * 16;    // 0,16,32,48
    const float* kbase = g_qkv + (size_t)(b * L + rJ) * QKV + D + h * DH + segk;
    const float* vbase = g_qkv + (size_t)(b * L + rJ) * QKV + 2 * D + h * DH + segk;

    float4 kreg[4];
#pragma unroll
    for (int u = 0; u < 4; ++u) kreg[u] = *(const float4*)(kbase + 4 * u);
    __syncthreads();

    // ============ PHASE 1: logits ============
    for (int jc = 0; jc < 8; ++jc) {
#pragma unroll
        for (int u = 0; u < 4; ++u) {
            int c = segk + 4 * u;
            KV[(c + 0) * KST + rJ] = kreg[u].x;
            KV[(c + 1) * KST + rJ] = kreg[u].y;
            KV[(c + 2) * KST + rJ] = kreg[u].z;
            KV[(c + 3) * KST + rJ] = kreg[u].w;
        }
        __syncthreads();
        if (jc < 7) {
            const float* kb = kbase + (size_t)(jc + 1) * 128 * QKV;
#pragma unroll
            for (int u = 0; u < 4; ++u) kreg[u] = *(const float4*)(kb + 4 * u);
        }

        u64 acc2[2][2];
        acc2[0][0] = 0ull; acc2[0][1] = 0ull;
        acc2[1][0] = 0ull; acc2[1][1] = 0ull;

#pragma unroll 8
        for (int d = 0; d < 64; ++d) {
            const u64* ap = (const u64*)&QsT[d * 36 + ty * 4];
            u64 pa0 = ap[0], pa1 = ap[1];
            float2 bv = *(const float2*)&KV[d * KST + txx * 2];
            u64 pb0 = dup2(bv.x), pb1 = dup2(bv.y);
            acc2[0][0] = ffma2(pa0, pb0, acc2[0][0]);
            acc2[0][1] = ffma2(pa0, pb1, acc2[0][1]);
            acc2[1][0] = ffma2(pa1, pb0, acc2[1][0]);
            acc2[1][1] = ffma2(pa1, pb1, acc2[1][1]);
        }

        const int jb = jc * 128 + txx * 2;
#pragma unroll
        for (int p = 0; p < 2; ++p) {
            float2 c0 = up2(acc2[p][0]);   // (row even, row odd) @ j = jb
            float2 c1 = up2(acc2[p][1]);   // @ j = jb+1
#pragma unroll
            for (int e = 0; e < 2; ++e) {
                const int il = ty * 4 + 2 * p + e;
                const int gi = i0 + il;
                const float* brow = biasW + il * 132;
                int r0 = min(max(jb + 0 - gi, -MREL), MREL) + MREL;
                int r1 = min(max(jb + 1 - gi, -MREL), MREL) + MREL;
                float2 o;
                o.x = (e ? c0.y : c0.x) + brow[r0];
                o.y = (e ? c1.y : c1.x) + brow[r1];
                *(float2*)&Sb[il * SBS + jb] = o;
            }
        }
        __syncthreads();
    }

    // ============ PHASE 2: softmax + raw wsum (16 lanes per row) ============
    {
        const int row = tid >> 4;     // 0..31
        const int ts = tid & 15;
        const int gi = i0 + row;
        float* srow = Sb + row * SBS;

        float m = -3.0e38f;
#pragma unroll 16
        for (int c = 0; c < 16; ++c) {
            float4 v = *(const float4*)&srow[ts * 4 + c * 64];
            m = fmaxf(m, fmaxf(fmaxf(v.x, v.y), fmaxf(v.z, v.w)));
        }
#pragma unroll
        for (int o = 8; o > 0; o >>= 1)
            m = fmaxf(m, __shfl_xor_sync(0xffffffffu, m, o));

        float s = 0.0f;
#pragma unroll 16
        for (int c = 0; c < 16; ++c) {
            float4 v = *(float4*)&srow[ts * 4 + c * 64];
            v.x = __expf(v.x - m); v.y = __expf(v.y - m);
            v.z = __expf(v.z - m); v.w = __expf(v.w - m);
            *(float4*)&srow[ts * 4 + c * 64] = v;
            s += v.x + v.y + v.z + v.w;
        }
#pragma unroll
        for (int o = 8; o > 0; o >>= 1) s += __shfl_xor_sync(0xffffffffu, s, o);
        if (ts == 0) invS[row] = 1.0f / s;

        float hp = 0.0f, tp = 0.0f;
        for (int j = ts; j <= gi - MREL; j += 16) hp += srow[j];
        for (int j = gi + MREL + ts; j < L; j += 16) tp += srow[j];
#pragma unroll
        for (int o = 8; o > 0; o >>= 1) {
            hp += __shfl_xor_sync(0xffffffffu, hp, o);
            tp += __shfl_xor_sync(0xffffffffu, tp, o);
        }
        __syncthreads();   // all exp writes done; biasW free for reuse

        float* wrow = biasW + row * 132;
#pragma unroll
        for (int k = 0; k < 8; ++k) {
            int r = 1 + ts * 8 + k;
            if (r < 128) {
                int j = gi + r - 64;
                wrow[r] = (j >= 0 && j < L) ? srow[j] : 0.0f;
            }
        }
        if (ts == 0) {
            wrow[0] = hp;
            wrow[128] = tp;
        }
    }

    // ============ PHASE 3: O = exp @ V (thread = 4i x 1d) ============
    u64 vacc[4];
#pragma unroll
    for (int i = 0; i < 4; ++i) vacc[i] = 0ull;

    const float* wr0 = Sb + (ty * 4 + 0) * SBS;
    const float* wr1 = Sb + (ty * 4 + 1) * SBS;
    const float* wr2 = Sb + (ty * 4 + 2) * SBS;
    const float* wr3 = Sb + (ty * 4 + 3) * SBS;
    const int dd = txx;    // 0..63

    float4 vreg[4];
#pragma unroll
    for (int u = 0; u < 4; ++u) vreg[u] = *(const float4*)(vbase + 4 * u);
    __syncthreads();   // wsum writes done; KV free for V staging

    for (int jc = 0; jc < 8; ++jc) {
#pragma unroll
        for (int u = 0; u < 4; ++u) {
            int c = segk + 4 * u;
            KV[(c + 0) * VST + rJ] = vreg[u].x;
            KV[(c + 1) * VST + rJ] = vreg[u].y;
            KV[(c + 2) * VST + rJ] = vreg[u].z;
            KV[(c + 3) * VST + rJ] = vreg[u].w;
        }
        __syncthreads();
        if (jc < 7) {
            const float* vb = vbase + (size_t)(jc + 1) * 128 * QKV;
#pragma unroll
            for (int u = 0; u < 4; ++u) vreg[u] = *(const float4*)(vb + 4 * u);
        }

        const int jbase = jc * 128;
        const float* vp = KV + dd * VST;
#pragma unroll 4
        for (int jq = 0; jq < 128; jq += 4) {
            const int j = jbase + jq;
            u64 va0 = *(const u64*)(vp + jq);
            u64 va1 = *(const u64*)(vp + jq + 2);
            u64 w0a = *(const u64*)(wr0 + j), w0b = *(const u64*)(wr0 + j + 2);
            u64 w1a = *(const u64*)(wr1 + j), w1b = *(const u64*)(wr1 + j + 2);
            u64 w2a = *(const u64*)(wr2 + j), w2b = *(const u64*)(wr2 + j + 2);
            u64 w3a = *(const u64*)(wr3 + j), w3b = *(const u64*)(wr3 + j + 2);
            vacc[0] = ffma2(w0a, va0, vacc[0]);
            vacc[0] = ffma2(w0b, va1, vacc[0]);
            vacc[1] = ffma2(w1a, va0, vacc[1]);
            vacc[1] = ffma2(w1b, va1, vacc[1]);
            vacc[2] = ffma2(w2a, va0, vacc[2]);
            vacc[2] = ffma2(w2b, va1, vacc[2]);
            vacc[3] = ffma2(w3a, va0, vacc[3]);
            vacc[3] = ffma2(w3b, va1, vacc[3]);
        }
        __syncthreads();
    }

    // ============ PHASE 4: rel_v epilogue ============
    for (int e = tid; e < R * 64; e += 512) {
        int r = e >> 6, d = e & 63;
        KV[d * VST + r] = relv[e];
    }
    __syncthreads();

    {
        const float* u0 = biasW + (ty * 4 + 0) * 132;
        const float* u1 = biasW + (ty * 4 + 1) * 132;
        const float* u2 = biasW + (ty * 4 + 2) * 132;
        const float* u3 = biasW + (ty * 4 + 3) * 132;
        const float* vp = KV + dd * VST;
#pragma unroll 4
        for (int rq = 0; rq < 128; rq += 4) {
            u64 va0 = *(const u64*)(vp + rq);
            u64 va1 = *(const u64*)(vp + rq + 2);
            u64 w0a = *(const u64*)(u0 + rq), w0b = *(const u64*)(u0 + rq + 2);
            u64 w1a = *(const u64*)(u1 + rq), w1b = *(const u64*)(u1 + rq + 2);
            u64 w2a = *(const u64*)(u2 + rq), w2b = *(const u64*)(u2 + rq + 2);
            u64 w3a = *(const u64*)(u3 + rq), w3b = *(const u64*)(u3 + rq + 2);
            vacc[0] = ffma2(w0a, va0, vacc[0]);
            vacc[0] = ffma2(w0b, va1, vacc[0]);
            vacc[1] = ffma2(w1a, va0, vacc[1]);
            vacc[1] = ffma2(w1b, va1, vacc[1]);
            vacc[2] = ffma2(w2a, va0, vacc[2]);
            vacc[2] = ffma2(w2b, va1, vacc[2]);
            vacc[3] = ffma2(w3a, va0, vacc[3]);
            vacc[3] = ffma2(w3b, va1, vacc[3]);
        }
    }

    // ---- writeout: 4 rows x 1 d per thread ----
    const float vt = KV[dd * VST + 128];   // relvT[dd][128]
#pragma unroll
    for (int i = 0; i < 4; ++i) {
        const int il = ty * 4 + i;
        const int gi = i0 + il;
        const float wt = biasW[il * 132 + 128];
        const float iv = invS[il];
        float2 sa = up2(vacc[i]);
        float o0 = (sa.x + sa.y + wt * vt) * iv;
        g_o[(size_t)(b * L + gi) * D + h * DH + dd] = o0;
    }
}

// ---------------------------------------------------------------------------
// Launch
// ---------------------------------------------------------------------------
extern "C" void kernel_launch(void* const* d_in, const int* in_sizes, int n_in,
                              void* d_out, int out_size) {
    const float* x    = (const float*)d_in[0];
    const float* Wq   = (const float*)d_in[1];
    const float* Wk   = (const float*)d_in[2];
    const float* Wv   = (const float*)d_in[3];
    const float* Wo   = (const float*)d_in[4];
    const float* relk = (const float*)d_in[5];
    const float* relv = (const float*)d_in[6];
    float* out = (float*)d_out;

    float *pqkv, *po;
    cudaGetSymbolAddress((void**)&pqkv, g_qkv);
    cudaGetSymbolAddress((void**)&po, g_o);
    bf16 *xh, *xl, *wh3, *wl3, *woh, *wol;
    cudaGetSymbolAddress((void**)&xh, g_xh);
    cudaGetSymbolAddress((void**)&xl, g_xl);
    cudaGetSymbolAddress((void**)&wh3, g_wh3);
    cudaGetSymbolAddress((void**)&wl3, g_wl3);
    cudaGetSymbolAddress((void**)&woh, g_woh);
    cudaGetSymbolAddress((void**)&wol, g_wol);

    cudaFuncSetAttribute(mega_attn_kernel,
                         cudaFuncAttributeMaxDynamicSharedMemorySize,
                         (int)FUSED_SMEM);
    cudaFuncSetAttribute(hgemm3x,
                         cudaFuncAttributeMaxDynamicSharedMemorySize,
                         (int)HG_SMEM);

    const dim3 gqkv(QKV / 128, NT / 128);   // (24, 16) = 384 CTAs
    const dim3 gout(D / 128, NT / 128);     // (8, 16)  = 128 CTAs
    const dim3 gt(32, 32);
    const dim3 gt3(32, 32, 3);
    const dim3 bt(32, 8);
    const int splitBlocks = (NT * D) / (256 * 4);   // 2048

    // launch 0: x split (reused across qkv)
    split_kernel<<<splitBlocks, 256>>>(x, xh, xl);
    // launch 1: batched Wq/Wk/Wv transpose+split
    splitT3_kernel<<<gt3, bt>>>(Wq, Wk, Wv, wh3, wl3);
    // launch 2: Wo transpose+split (independent)
    splitT_kernel<<<gt, bt>>>(Wo, woh, wol);
    // launch 3: ONE fused qkv GEMM (2048 x 3072 x 1024)
    hgemm3x<<<gqkv, 256, HG_SMEM>>>(xh, xl, wh3, wl3, pqkv, NT, QKV, D);
    // launch 4: relq bias table
    relq_kernel<<<dim3(L / 32, BH), 256>>>(relk);
    // launch 5: fused attention (now 512 threads)
    mega_attn_kernel<<<dim3(L / 32, BH), 512, FUSED_SMEM>>>(relv);
    // launches 6-7: output projection
    split_kernel<<<splitBlocks, 256>>>(po, xh, xl);
    hgemm3x<<<gout, 256, HG_SMEM>>>(xh, xl, woh, wol, out, NT, D, D);
}

// round 15
// speedup vs baseline: 1.3101x; 1.3101x over previous
#include <cuda_runtime.h>
#include <cuda_bf16.h>
#include <cstdint>

// ---------------------------------------------------------------------------
// MultiHead2DAttention (Shaw relative positions, T2T variant)
// B=2, L=1024, D=1024, H=16, DH=64, M=64, R=129
// Round 14: mega-fused attention moves its two GEMM phases (logits QK^T and
// probs@V) onto tensor cores via the compensated bf16 mma.sync scheme proven
// in hgemm3x. Q/K split on the fly; V pre-transposed+split by vt_kernel;
// softmax probs split per chunk; rel_v epilogue stays fp32. Everything else
// identical to the best passing R12 kernel (776us).
// ---------------------------------------------------------------------------

namespace {
constexpr int B  = 2;
constexpr int L  = 1024;
constexpr int D  = 1024;
constexpr int H  = 16;
constexpr int DH = 64;
constexpr int MREL = 64;
constexpr int R  = 2 * MREL + 1;   // 129
constexpr int RP = 132;            // padded row stride for relq
constexpr int NT = B * L;          // 2048
constexpr int BH = B * H;          // 32
constexpr int QKV = 3 * D;         // 3072
}

typedef __nv_bfloat16 bf16;
typedef unsigned long long u64;
typedef unsigned int u32;

// Scratch buffers (device globals)
__device__ float g_qkv[(size_t)NT * QKV];
__device__ float g_o[NT * D];
__device__ float g_relq[(size_t)BH * L * RP];

// bf16 split buffers (projection GEMMs)
__device__ bf16 g_xh[NT * D];
__device__ bf16 g_xl[NT * D];
__device__ bf16 g_wh3[(size_t)3 * D * D];
__device__ bf16 g_wl3[(size_t)3 * D * D];
__device__ bf16 g_woh[D * D];
__device__ bf16 g_wol[D * D];

// pre-transposed + split V: [bh][64 d][1024 j]
__device__ bf16 g_vth[(size_t)BH * 64 * 1024];
__device__ bf16 g_vtl[(size_t)BH * 64 * 1024];

// ---------------------------------------------------------------------------
// helpers
// ---------------------------------------------------------------------------
__device__ __forceinline__ u64 pk2(float x, float y) {
    u64 r;
    asm("mov.b64 %0, {%1, %2};" : "=l"(r) : "f"(x), "f"(y));
    return r;
}
__device__ __forceinline__ u64 dup2(float x) { return pk2(x, x); }
__device__ __forceinline__ u64 ffma2(u64 a, u64 b, u64 c) {
    u64 d;
    asm("fma.rn.f32x2 %0, %1, %2, %3;" : "=l"(d) : "l"(a), "l"(b), "l"(c));
    return d;
}
__device__ __forceinline__ float2 up2(u64 v) {
    float2 f;
    asm("mov.b64 {%0, %1}, %2;" : "=f"(f.x), "=f"(f.y) : "l"(v));
    return f;
}
__device__ __forceinline__ void mma16816(float* c, const u32* a, const u32* b) {
    asm volatile(
        "mma.sync.aligned.m16n8k16.row.col.f32.bf16.bf16.f32 "
        "{%0,%1,%2,%3},{%4,%5,%6,%7},{%8,%9},{%0,%1,%2,%3};"
        : "+f"(c[0]), "+f"(c[1]), "+f"(c[2]), "+f"(c[3])
        : "r"(a[0]), "r"(a[1]), "r"(a[2]), "r"(a[3]), "r"(b[0]), "r"(b[1]));
}
__device__ __forceinline__ void cp16(u32 smem_addr, const void* gptr) {
    asm volatile("cp.async.cg.shared.global [%0], [%1], 16;"
                 :: "r"(smem_addr), "l"(gptr));
}
// pack 2 floats -> bf16x2 (hi) and residual (lo)
__device__ __forceinline__ u32 pkh2(float x, float y) {
    __nv_bfloat162 p(__float2bfloat16(x), __float2bfloat16(y));
    return *(u32*)&p;
}
__device__ __forceinline__ u32 pkl2(float x, float y) {
    bf16 hx = __float2bfloat16(x), hy = __float2bfloat16(y);
    __nv_bfloat162 p(__float2bfloat16(x - __bfloat162float(hx)),
                     __float2bfloat16(y - __bfloat162float(hy)));
    return *(u32*)&p;
}

// ---------------------------------------------------------------------------
// split / splitT3 / splitT  (unchanged)
// ---------------------------------------------------------------------------
__global__ __launch_bounds__(256) void split_kernel(const float* __restrict__ src,
                                                    bf16* __restrict__ hi,
                                                    bf16* __restrict__ lo) {
    int i = (blockIdx.x * 256 + threadIdx.x) * 4;
    float4 v = *(const float4*)(src + i);
    __nv_bfloat162* hp = (__nv_bfloat162*)(hi + i);
    __nv_bfloat162* lp = (__nv_bfloat162*)(lo + i);
    u32 h0 = pkh2(v.x, v.y), h1 = pkh2(v.z, v.w);
    u32 l0 = pkl2(v.x, v.y), l1 = pkl2(v.z, v.w);
    hp[0] = *(__nv_bfloat162*)&h0;
    hp[1] = *(__nv_bfloat162*)&h1;
    lp[0] = *(__nv_bfloat162*)&l0;
    lp[1] = *(__nv_bfloat162*)&l1;
}

__global__ void splitT3_kernel(const float* __restrict__ W0,
                               const float* __restrict__ W1,
                               const float* __restrict__ W2,
                               bf16* __restrict__ th, bf16* __restrict__ tl) {
    __shared__ float ts[32][33];
    const int tx = threadIdx.x, ty = threadIdx.y;
    const int n0 = blockIdx.x * 32, k0 = blockIdx.y * 32;
    const int z = blockIdx.z;
    const float* W = (z == 0) ? W0 : (z == 1) ? W1 : W2;
    for (int r = ty; r < 32; r += 8)
        ts[r][tx] = W[(size_t)(k0 + r) * D + n0 + tx];
    __syncthreads();
    const size_t zofs = (size_t)z * D * D;
    for (int r = ty; r < 32; r += 8) {
        float v = ts[tx][r];
        bf16 h = __float2bfloat16(v);
        bf16 l = __float2bfloat16(v - __bfloat162float(h));
        th[zofs + (size_t)(n0 + r) * D + k0 + tx] = h;
        tl[zofs + (size_t)(n0 + r) * D + k0 + tx] = l;
    }
}

__global__ void splitT_kernel(const float* __restrict__ W,
                              bf16* __restrict__ th, bf16* __restrict__ tl) {
    __shared__ float ts[32][33];
    const int tx = threadIdx.x, ty = threadIdx.y;
    const int n0 = blockIdx.x * 32, k0 = blockIdx.y * 32;
    for (int r = ty; r < 32; r += 8)
        ts[r][tx] = W[(size_t)(k0 + r) * D + n0 + tx];
    __syncthreads();
    for (int r = ty; r < 32; r += 8) {
        float v = ts[tx][r];
        bf16 h = __float2bfloat16(v);
        bf16 l = __float2bfloat16(v - __bfloat162float(h));
        th[(size_t)(n0 + r) * D + k0 + tx] = h;
        tl[(size_t)(n0 + r) * D + k0 + tx] = l;
    }
}

// vt: V section of g_qkv -> transposed hi/lo bf16 [bh][d][j]
__global__ void vt_kernel(bf16* __restrict__ th, bf16* __restrict__ tl) {
    __shared__ float ts[32][33];
    const int tx = threadIdx.x, ty = threadIdx.y;
    const int j0 = blockIdx.x * 32, d0 = blockIdx.y * 32;
    const int bh = blockIdx.z, b = bh >> 4, h = bh & 15;
    for (int r = ty; r < 32; r += 8)
        ts[r][tx] = g_qkv[(size_t)(b * L + j0 + r) * QKV + 2 * D + h * DH + d0 + tx];
    __syncthreads();
    for (int r = ty; r < 32; r += 8) {
        float v = ts[tx][r];
        bf16 hh = __float2bfloat16(v);
        bf16 ll = __float2bfloat16(v - __bfloat162float(hh));
        size_t o = ((size_t)bh * 64 + d0 + r) * 1024 + j0 + tx;
        th[o] = hh;
        tl[o] = ll;
    }
}

// ---------------------------------------------------------------------------
// hgemm3x: unchanged from R12 (3-stage cp.async ring)
// ---------------------------------------------------------------------------
namespace {
constexpr int HG_STR = 24;
constexpr u32 HG_TB = 128 * HG_STR * 2;
constexpr u32 HG_STAGE_B = 4 * HG_TB;
constexpr u32 HG_SMEM = 3 * HG_STAGE_B;
}

__global__ __launch_bounds__(256) void hgemm3x(const bf16* __restrict__ Ah,
                                               const bf16* __restrict__ Al,
                                               const bf16* __restrict__ Bh,
                                               const bf16* __restrict__ Bl,
                                               float* __restrict__ C,
                                               int Md, int Nd, int Kd) {
    extern __shared__ __align__(16) bf16 hsm[];
    const u32 sbase = (u32)__cvta_generic_to_shared(hsm);

    const int tid = threadIdx.x;
    const int bm = blockIdx.y * 128;
    const int bn = blockIdx.x * 128;
    const int wid = tid >> 5;
    const int lane = tid & 31;
    const int g = lane >> 2;
    const int tg = lane & 3;
    const int wm = (wid & 1) * 64;
    const int wn = (wid >> 1) * 32;

    const int lrow = tid >> 1;
    const int lseg = (tid & 1) * 8;
    const size_t aoff = (size_t)(bm + lrow) * Kd + lseg;
    const size_t boff = (size_t)(bn + lrow) * Kd + lseg;
    const u32 sdst = (u32)(lrow * HG_STR + lseg) * 2;

    float acc[4][4][4];
#pragma unroll
    for (int ma = 0; ma < 4; ++ma)
#pragma unroll
        for (int na = 0; na < 4; ++na)
#pragma unroll
            for (int e = 0; e < 4; ++e) acc[ma][na][e] = 0.0f;

    const int nT = Kd / 16;

    auto stage_tile = [&](int kt, int slot) {
        const u32 o = sbase + (u32)slot * HG_STAGE_B + sdst;
        const size_t ko = (size_t)kt * 16;
        cp16(o + 0 * HG_TB, Ah + aoff + ko);
        cp16(o + 1 * HG_TB, Al + aoff + ko);
        cp16(o + 2 * HG_TB, Bh + boff + ko);
        cp16(o + 3 * HG_TB, Bl + boff + ko);
        asm volatile("cp.async.commit_group;");
    };

    stage_tile(0, 0);
    if (nT > 1) stage_tile(1, 1);

    int slot = 0;
    for (int kt = 0; kt < nT; ++kt) {
        if (kt + 1 < nT) {
            asm volatile("cp.async.wait_group 1;" ::: "memory");
        } else {
            asm volatile("cp.async.wait_group 0;" ::: "memory");
        }
        __syncthreads();
        if (kt + 2 < nT) stage_tile(kt + 2, (slot + 2) % 3);

        const bf16* Abh = hsm + (size_t)slot * (HG_STAGE_B / 2);
        const bf16* Abl = Abh + HG_TB / 2;
        const bf16* Bbh = Abh + 2 * (HG_TB / 2);
        const bf16* Bbl = Abh + 3 * (HG_TB / 2);

        u32 ah[4][4], al[4][4], bh[4][2], bl[4][2];
#pragma unroll
        for (int ma = 0; ma < 4; ++ma) {
            const int r0 = (wm + ma * 16 + g) * HG_STR + 2 * tg;
            const int r1 = r0 + 8 * HG_STR;
            ah[ma][0] = *(const u32*)(Abh + r0);
            ah[ma][1] = *(const u32*)(Abh + r1);
            ah[ma][2] = *(const u32*)(Abh + r0 + 8);
            ah[ma][3] = *(const u32*)(Abh + r1 + 8);
            al[ma][0] = *(const u32*)(Abl + r0);
            al[ma][1] = *(const u32*)(Abl + r1);
            al[ma][2] = *(const u32*)(Abl + r0 + 8);
            al[ma][3] = *(const u32*)(Abl + r1 + 8);
        }
#pragma unroll
        for (int na = 0; na < 4; ++na) {
            const int c0 = (wn + na * 8 + g) * HG_STR + 2 * tg;
            bh[na][0] = *(const u32*)(Bbh + c0);
            bh[na][1] = *(const u32*)(Bbh + c0 + 8);
            bl[na][0] = *(const u32*)(Bbl + c0);
            bl[na][1] = *(const u32*)(Bbl + c0 + 8);
        }

#pragma unroll
        for (int ma = 0; ma < 4; ++ma)
#pragma unroll
            for (int na = 0; na < 4; ++na)
                mma16816(acc[ma][na], ah[ma], bh[na]);
#pragma unroll
        for (int ma = 0; ma < 4; ++ma)
#pragma unroll
            for (int na = 0; na < 4; ++na)
                mma16816(acc[ma][na], ah[ma], bl[na]);
#pragma unroll
        for (int ma = 0; ma < 4; ++ma)
#pragma unroll
            for (int na = 0; na < 4; ++na)
                mma16816(acc[ma][na], al[ma], bh[na]);

        slot = (slot + 1) % 3;
    }

#pragma unroll
    for (int ma = 0; ma < 4; ++ma) {
#pragma unroll
        for (int na = 0; na < 4; ++na) {
            const int r0 = bm + wm + ma * 16 + g;
            const int c = bn + wn + na * 8 + 2 * tg;
            *(float2*)(C + (size_t)r0 * Nd + c) =
                make_float2(acc[ma][na][0], acc[ma][na][1]);
            *(float2*)(C + (size_t)(r0 + 8) * Nd + c) =
                make_float2(acc[ma][na][2], acc[ma][na][3]);
        }
    }
}

// ---------------------------------------------------------------------------
// relq (unchanged from R12)
// ---------------------------------------------------------------------------
__global__ __launch_bounds__(256) void relq_kernel(const float* __restrict__ relk) {
    __shared__ __align__(16) float qsT[64][36];
    __shared__ __align__(16) float tsT[64][132];

    const int tid = threadIdx.x;
    const int bh = blockIdx.y;
    const int b = bh >> 4;
    const int h = bh & 15;
    const int i0 = blockIdx.x * 32;
    const int tx = tid & 31;
    const int ty = tid >> 5;
    const float QS = 0.125f;

    {
        const int rI = tid >> 3;
        const int seg = (tid & 7) * 8;
        const float* qb = g_qkv + (size_t)(b * L + i0 + rI) * QKV + h * DH + seg;
        float4 v0 = *(const float4*)qb;
        float4 v1 = *(const float4*)(qb + 4);
        qsT[seg + 0][rI] = v0.x * QS; qsT[seg + 1][rI] = v0.y * QS;
        qsT[seg + 2][rI] = v0.z * QS; qsT[seg + 3][rI] = v0.w * QS;
        qsT[seg + 4][rI] = v1.x * QS; qsT[seg + 5][rI] = v1.y * QS;
        qsT[seg + 6][rI] = v1.z * QS; qsT[seg + 7][rI] = v1.w * QS;
    }
    for (int e = tid; e < R * 64; e += 256) {
        int r = e >> 6, d = e & 63;
        tsT[d][r] = relk[e];
    }
    __syncthreads();

    u64 acc2[2][4];
#pragma unroll
    for (int p = 0; p < 2; ++p)
#pragma unroll
        for (int j = 0; j < 4; ++j) acc2[p][j] = 0ull;

#pragma unroll 8
    for (int d = 0; d < 64; ++d) {
        const u64* ap = (const u64*)&qsT[d][ty * 4];
        u64 pa0 = ap[0], pa1 = ap[1];
        float4 bv = *(const float4*)&tsT[d][tx * 4];
        u64 pb0 = dup2(bv.x), pb1 = dup2(bv.y), pb2 = dup2(bv.z), pb3 = dup2(bv.w);
        acc2[0][0] = ffma2(pa0, pb0, acc2[0][0]);
        acc2[0][1] = ffma2(pa0, pb1, acc2[0][1]);
        acc2[0][2] = ffma2(pa0, pb2, acc2[0][2]);
        acc2[0][3] = ffma2(pa0, pb3, acc2[0][3]);
        acc2[1][0] = ffma2(pa1, pb0, acc2[1][0]);
        acc2[1][1] = ffma2(pa1, pb1, acc2[1][1]);
        acc2[1][2] = ffma2(pa1, pb2, acc2[1][2]);
        acc2[1][3] = ffma2(pa1, pb3, acc2[1][3]);
    }

#pragma unroll
    for (int p = 0; p < 2; ++p) {
        float2 c0 = up2(acc2[p][0]);
        float2 c1 = up2(acc2[p][1]);
        float2 c2 = up2(acc2[p][2]);
        float2 c3 = up2(acc2[p][3]);
        int gi = i0 + ty * 4 + 2 * p;
        float* o0 = g_relq + ((size_t)bh * L + gi) * RP + tx * 4;
        float* o1 = o0 + RP;
        *(float4*)o0 = make_float4(c0.x, c1.x, c2.x, c3.x);
        *(float4*)o1 = make_float4(c0.y, c1.y, c2.y, c3.y);
    }

    if (tid < 32) {
        float s = 0.0f;
#pragma unroll 8
        for (int d = 0; d < 64; ++d) s += qsT[d][tid] * tsT[d][128];
        g_relq[((size_t)bh * L + i0 + tid) * RP + 128] = s;
    }
}

// ---------------------------------------------------------------------------
// MEGA-fused attention v2: tensor-core logits + AV, fp32 softmax/rel_v.
// 256 threads, 8 warps. grid (L/32, BH).
// ---------------------------------------------------------------------------
namespace {
constexpr int SBS = 1032;
constexpr int KQS = 88;    // K/Q bf16 stride (176B rows: aligned + conflict-free)
constexpr int WVS = 136;   // W/V bf16 stride (272B rows)
constexpr int SB_F = 32 * SBS;          // 33024 floats
constexpr int KV_F = 11264;             // 45056B region (K / V / relv)
constexpr int QW_F = 4352;              // 17408B region (Q / W / Osm)
constexpr int BW_F = 32 * 132;          // 4224
constexpr u32 MEGA_SMEM = (SB_F + KV_F + QW_F + BW_F + 32) * 4;   // 211,584B
}

__global__ __launch_bounds__(256, 1) void mega_attn_kernel(
        const float* __restrict__ relv,
        const bf16* __restrict__ vth, const bf16* __restrict__ vtl) {
    extern __shared__ float fs[];
    float* Sb    = fs;                   // [32][SBS]
    float* KVf   = Sb + SB_F;
    float* QWf   = KVf + KV_F;
    float* biasW = QWf + QW_F;           // [32][132]
    float* invS  = biasW + BW_F;         // [32]

    bf16* Kh = (bf16*)KVf;               // [128][88]
    bf16* Kl = Kh + 128 * KQS;
    bf16* Vh = (bf16*)KVf;               // [64][136] (phase 3)
    bf16* Vl = Vh + 64 * WVS;
    float* relvS = KVf;                  // [129][68] (phase 4)
    bf16* Qh = (bf16*)QWf;               // [32][88]
    bf16* Ql = Qh + 32 * KQS;
    bf16* Wh = (bf16*)QWf;               // [32][136] (phase 3)
    bf16* Wl = Wh + 32 * WVS;
    float* Osm = QWf;                    // [32][68] (after phase 3)

    const int tid = threadIdx.x;
    const int bh = blockIdx.y, b = bh >> 4, h = bh & 15;
    const int i0 = blockIdx.x * 32;
    const int w = tid >> 5, lane = tid & 31, g = lane >> 2, tg = lane & 3;

    // ---- stage Q hi/lo (unscaled; 0.125 applied in logits epilogue) ----
    {
        const int rI = tid >> 3, seg = (tid & 7) * 8;
        const float* qb = g_qkv + (size_t)(b * L + i0 + rI) * QKV + h * DH + seg;
        float4 v0 = ((const float4*)qb)[0];
        float4 v1 = ((const float4*)qb)[1];
        uint4 hh = make_uint4(pkh2(v0.x, v0.y), pkh2(v0.z, v0.w),
                              pkh2(v1.x, v1.y), pkh2(v1.z, v1.w));
        uint4 ll = make_uint4(pkl2(v0.x, v0.y), pkl2(v0.z, v0.w),
                              pkl2(v1.x, v1.y), pkl2(v1.z, v1.w));
        *(uint4*)(Qh + rI * KQS + seg) = hh;
        *(uint4*)(Ql + rI * KQS + seg) = ll;
    }
    // ---- stage bias ----
    for (int e = tid; e < 32 * 132; e += 256) {
        int il = e / 132, r = e - il * 132;
        biasW[e] = (r < R) ? g_relq[((size_t)bh * L + i0 + il) * RP + r] : 0.0f;
    }

    // K prefetch (chunk 0)
    const int rJ = tid >> 1, segk = (tid & 1) * 32;
    const float* kbase = g_qkv + (size_t)(b * L + rJ) * QKV + D + h * DH + segk;
    float4 kreg[8];
#pragma unroll
    for (int u = 0; u < 8; ++u) kreg[u] = *(const float4*)(kbase + 4 * u);
    __syncthreads();

    // ================= PHASE 1: logits via mma =================
    const int m0 = (w & 1) * 16;
    const int jg = (w >> 1) * 32;
    for (int jc = 0; jc < 8; ++jc) {
        // store K chunk hi/lo
#pragma unroll
        for (int u = 0; u < 4; ++u) {
            uint4 hh = make_uint4(
                pkh2(kreg[2 * u].x, kreg[2 * u].y), pkh2(kreg[2 * u].z, kreg[2 * u].w),
                pkh2(kreg[2 * u + 1].x, kreg[2 * u + 1].y), pkh2(kreg[2 * u + 1].z, kreg[2 * u + 1].w));
            uint4 ll = make_uint4(
                pkl2(kreg[2 * u].x, kreg[2 * u].y), pkl2(kreg[2 * u].z, kreg[2 * u].w),
                pkl2(kreg[2 * u + 1].x, kreg[2 * u + 1].y), pkl2(kreg[2 * u + 1].z, kreg[2 * u + 1].w));
            *(uint4*)(Kh + rJ * KQS + segk + 8 * u) = hh;
            *(uint4*)(Kl + rJ * KQS + segk + 8 * u) = ll;
        }
        __syncthreads();
        if (jc < 7) {
            const float* kb = kbase + (size_t)(jc + 1) * 128 * QKV;
#pragma unroll
            for (int u = 0; u < 8; ++u) kreg[u] = *(const float4*)(kb + 4 * u);
        }

        float acc[4][4];
#pragma unroll
        for (int n = 0; n < 4; ++n)
#pragma unroll
            for (int e = 0; e < 4; ++e) acc[n][e] = 0.0f;

#pragma unroll
        for (int kk = 0; kk < 4; ++kk) {
            const int ko = kk * 16 + 2 * tg;
            const bf16* qp = Qh + (m0 + g) * KQS + ko;
            const bf16* qlp = Ql + (m0 + g) * KQS + ko;
            u32 ah[4], al4[4];
            ah[0] = *(const u32*)qp;
            ah[1] = *(const u32*)(qp + 8 * KQS);
            ah[2] = *(const u32*)(qp + 8);
            ah[3] = *(const u32*)(qp + 8 * KQS + 8);
            al4[0] = *(const u32*)qlp;
            al4[1] = *(const u32*)(qlp + 8 * KQS);
            al4[2] = *(const u32*)(qlp + 8);
            al4[3] = *(const u32*)(qlp + 8 * KQS + 8);
            u32 bh_[4][2], bl_[4][2];
#pragma unroll
            for (int n = 0; n < 4; ++n) {
                const bf16* kp = Kh + (jg + n * 8 + g) * KQS + ko;
                const bf16* klp = Kl + (jg + n * 8 + g) * KQS + ko;
                bh_[n][0] = *(const u32*)kp;
                bh_[n][1] = *(const u32*)(kp + 8);
                bl_[n][0] = *(const u32*)klp;
                bl_[n][1] = *(const u32*)(klp + 8);
            }
#pragma unroll
            for (int n = 0; n < 4; ++n) mma16816(acc[n], ah, bh_[n]);
#pragma unroll
            for (int n = 0; n < 4; ++n) mma16816(acc[n], ah, bl_[n]);
#pragma unroll
            for (int n = 0; n < 4; ++n) mma16816(acc[n], al4, bh_[n]);
        }

        // epilogue: S = 0.125*acc + bias -> Sb
        const int jb0 = jc * 128 + jg;
#pragma unroll
        for (int n = 0; n < 4; ++n) {
#pragma unroll
            for (int hh = 0; hh < 2; ++hh) {
                const int il = m0 + g + 8 * hh;
                const int gi = i0 + il;
                const int jj = jb0 + n * 8 + 2 * tg;
                const float* brow = biasW + il * 132;
                int r0 = min(max(jj - gi, -MREL), MREL) + MREL;
                int r1 = min(max(jj + 1 - gi, -MREL), MREL) + MREL;
                float2 o;
                o.x = acc[n][2 * hh] * 0.125f + brow[r0];
                o.y = acc[n][2 * hh + 1] * 0.125f + brow[r1];
                *(float2*)&Sb[il * SBS + jj] = o;
            }
        }
        __syncthreads();
    }

    // ================= PHASE 2: softmax + raw wsum =================
    {
        const int row = tid >> 3;
        const int ts = tid & 7;
        const int gi = i0 + row;
        float* srow = Sb + row * SBS;

        float m = -3.0e38f;
#pragma unroll 8
        for (int c = 0; c < 32; ++c) {
            float4 v = *(const float4*)&srow[ts * 4 + c * 32];
            m = fmaxf(m, fmaxf(fmaxf(v.x, v.y), fmaxf(v.z, v.w)));
        }
#pragma unroll
        for (int o = 4; o > 0; o >>= 1)
            m = fmaxf(m, __shfl_xor_sync(0xffffffffu, m, o));

        float s = 0.0f;
#pragma unroll 8
        for (int c = 0; c < 32; ++c) {
            float4 v = *(float4*)&srow[ts * 4 + c * 32];
            v.x = __expf(v.x - m); v.y = __expf(v.y - m);
            v.z = __expf(v.z - m); v.w = __expf(v.w - m);
            *(float4*)&srow[ts * 4 + c * 32] = v;
            s += v.x + v.y + v.z + v.w;
        }
#pragma unroll
        for (int o = 4; o > 0; o >>= 1) s += __shfl_xor_sync(0xffffffffu, s, o);
        if (ts == 0) invS[row] = 1.0f / s;

        float hp = 0.0f, tp = 0.0f;
        for (int j = ts; j <= gi - MREL; j += 8) hp += srow[j];
        for (int j = gi + MREL + ts; j < L; j += 8) tp += srow[j];
#pragma unroll
        for (int o = 4; o > 0; o >>= 1) {
            hp += __shfl_xor_sync(0xffffffffu, hp, o);
            tp += __shfl_xor_sync(0xffffffffu, tp, o);
        }
        __syncthreads();   // exp writes done; biasW free

        float* wrow = biasW + row * 132;
#pragma unroll
        for (int k = 0; k < 16; ++k) {
            int r = 1 + ts * 16 + k;
            if (r < 128) {
                int j = gi + r - 64;
                wrow[r] = (j >= 0 && j < L) ? srow[j] : 0.0f;
            }
        }
        if (ts == 0) {
            wrow[0] = hp;
            wrow[128] = tp;
        }
    }

    // ================= PHASE 3: O = exp @ V via mma =================
    const int dd = tid >> 2, js = (tid & 3) * 32;
    const bf16* vhg = vth + ((size_t)bh * 64 + dd) * 1024 + js;
    const bf16* vlg = vtl + ((size_t)bh * 64 + dd) * 1024 + js;
    uint4 vph[4], vpl[4];
#pragma unroll
    for (int u = 0; u < 4; ++u) {
        vph[u] = *(const uint4*)(vhg + 8 * u);
        vpl[u] = *(const uint4*)(vlg + 8 * u);
    }
    __syncthreads();   // phase 2 fully done (wsum written; Sb final)

    float acc3[2][4];
#pragma unroll
    for (int n = 0; n < 2; ++n)
#pragma unroll
        for (int e = 0; e < 4; ++e) acc3[n][e] = 0.0f;
    const int dg = (w >> 1) * 16;

    for (int jc = 0; jc < 8; ++jc) {
        // store V chunk
#pragma unroll
        for (int u = 0; u < 4; ++u) {
            *(uint4*)(Vh + dd * WVS + js + 8 * u) = vph[u];
            *(uint4*)(Vl + dd * WVS + js + 8 * u) = vpl[u];
        }
        // convert W chunk (Sb fp32 -> Wh/Wl bf16)
        {
            const int rr = tid & 31, cs = (tid >> 5) * 16;
            const float* sp = Sb + rr * SBS + jc * 128 + cs;
            float4 x0 = ((const float4*)sp)[0];
            float4 x1 = ((const float4*)sp)[1];
            float4 x2 = ((const float4*)sp)[2];
            float4 x3 = ((const float4*)sp)[3];
            *(uint4*)(Wh + rr * WVS + cs) = make_uint4(
                pkh2(x0.x, x0.y), pkh2(x0.z, x0.w), pkh2(x1.x, x1.y), pkh2(x1.z, x1.w));
            *(uint4*)(Wh + rr * WVS + cs + 8) = make_uint4(
                pkh2(x2.x, x2.y), pkh2(x2.z, x2.w), pkh2(x3.x, x3.y), pkh2(x3.z, x3.w));
            *(uint4*)(Wl + rr * WVS + cs) = make_uint4(
                pkl2(x0.x, x0.y), pkl2(x0.z, x0.w), pkl2(x1.x, x1.y), pkl2(x1.z, x1.w));
            *(uint4*)(Wl + rr * WVS + cs + 8) = make_uint4(
                pkl2(x2.x, x2.y), pkl2(x2.z, x2.w), pkl2(x3.x, x3.y), pkl2(x3.z, x3.w));
        }
        __syncthreads();
        if (jc < 7) {
            const int jn = (jc + 1) * 128;
#pragma unroll
            for (int u = 0; u < 4; ++u) {
                vph[u] = *(const uint4*)(vhg + jn + 8 * u);
                vpl[u] = *(const uint4*)(vlg + jn + 8 * u);
            }
        }

#pragma unroll
        for (int kk = 0; kk < 8; ++kk) {
            const int ko = kk * 16 + 2 * tg;
            const bf16* wp = Wh + (m0 + g) * WVS + ko;
            const bf16* wlp = Wl + (m0 + g) * WVS + ko;
            u32 ah[4], al4[4];
            ah[0] = *(const u32*)wp;
            ah[1] = *(const u32*)(wp + 8 * WVS);
            ah[2] = *(const u32*)(wp + 8);
            ah[3] = *(const u32*)(wp + 8 * WVS + 8);
            al4[0] = *(const u32*)wlp;
            al4[1] = *(const u32*)(wlp + 8 * WVS);
            al4[2] = *(const u32*)(wlp + 8);
            al4[3] = *(const u32*)(wlp + 8 * WVS + 8);
            u32 bh_[2][2], bl_[2][2];
#pragma unroll
            for (int n = 0; n < 2; ++n) {
                const bf16* vp = Vh + (dg + n * 8 + g) * WVS + ko;
                const bf16* vlp = Vl + (dg + n * 8 + g) * WVS + ko;
                bh_[n][0] = *(const u32*)vp;
                bh_[n][1] = *(const u32*)(vp + 8);
                bl_[n][0] = *(const u32*)vlp;
                bl_[n][1] = *(const u32*)(vlp + 8);
            }
#pragma unroll
            for (int n = 0; n < 2; ++n) mma16816(acc3[n], ah, bh_[n]);
#pragma unroll
            for (int n = 0; n < 2; ++n) mma16816(acc3[n], ah, bl_[n]);
#pragma unroll
            for (int n = 0; n < 2; ++n) mma16816(acc3[n], al4, bh_[n]);
        }
        __syncthreads();
    }

    // write O accumulators to smem; stage relv
#pragma unroll
    for (int n = 0; n < 2; ++n) {
#pragma unroll
        for (int hh = 0; hh < 2; ++hh) {
            const int il = m0 + g + 8 * hh;
            *(float2*)&Osm[il * 68 + dg + n * 8 + 2 * tg] =
                make_float2(acc3[n][2 * hh], acc3[n][2 * hh + 1]);
        }
    }
    for (int e = tid; e < R * 64; e += 256) {
        relvS[(e >> 6) * 68 + (e & 63)] = relv[e];
    }
    __syncthreads();

    // ================= PHASE 4: rel_v + writeout =================
    {
        const int ii = tid & 31, dg8 = (tid >> 5) * 8;
        const float* wrow = biasW + ii * 132;
        u64 a4[4] = {0ull, 0ull, 0ull, 0ull};
        for (int r = 0; r <= 128; ++r) {
            u64 wd = dup2(wrow[r]);
            const float* vr = relvS + r * 68 + dg8;
            a4[0] = ffma2(wd, *(const u64*)(vr + 0), a4[0]);
            a4[1] = ffma2(wd, *(const u64*)(vr + 2), a4[1]);
            a4[2] = ffma2(wd, *(const u64*)(vr + 4), a4[2]);
            a4[3] = ffma2(wd, *(const u64*)(vr + 6), a4[3]);
        }
        const float iv = invS[ii];
        const float* op = Osm + ii * 68 + dg8;
        float2 p0 = up2(a4[0]), p1 = up2(a4[1]), p2 = up2(a4[2]), p3 = up2(a4[3]);
        float4 o0 = make_float4((op[0] + p0.x) * iv, (op[1] + p0.y) * iv,
                                (op[2] + p1.x) * iv, (op[3] + p1.y) * iv);
        float4 o1 = make_float4((op[4] + p2.x) * iv, (op[5] + p2.y) * iv,
                                (op[6] + p3.x) * iv, (op[7] + p3.y) * iv);
        float* ob = g_o + (size_t)(b * L + i0 + ii) * D + h * DH + dg8;
        *(float4*)ob = o0;
        *(float4*)(ob + 4) = o1;
    }
}

// ---------------------------------------------------------------------------
// Launch
// ---------------------------------------------------------------------------
extern "C" void kernel_launch(void* const* d_in, const int* in_sizes, int n_in,
                              void* d_out, int out_size) {
    const float* x    = (const float*)d_in[0];
    const float* Wq   = (const float*)d_in[1];
    const float* Wk   = (const float*)d_in[2];
    const float* Wv   = (const float*)d_in[3];
    const float* Wo   = (const float*)d_in[4];
    const float* relk = (const float*)d_in[5];
    const float* relv = (const float*)d_in[6];
    float* out = (float*)d_out;

    float *pqkv, *po;
    cudaGetSymbolAddress((void**)&pqkv, g_qkv);
    cudaGetSymbolAddress((void**)&po, g_o);
    bf16 *xh, *xl, *wh3, *wl3, *woh, *wol, *vth, *vtl;
    cudaGetSymbolAddress((void**)&xh, g_xh);
    cudaGetSymbolAddress((void**)&xl, g_xl);
    cudaGetSymbolAddress((void**)&wh3, g_wh3);
    cudaGetSymbolAddress((void**)&wl3, g_wl3);
    cudaGetSymbolAddress((void**)&woh, g_woh);
    cudaGetSymbolAddress((void**)&wol, g_wol);
    cudaGetSymbolAddress((void**)&vth, g_vth);
    cudaGetSymbolAddress((void**)&vtl, g_vtl);

    cudaFuncSetAttribute(mega_attn_kernel,
                         cudaFuncAttributeMaxDynamicSharedMemorySize,
                         (int)MEGA_SMEM);
    cudaFuncSetAttribute(hgemm3x,
                         cudaFuncAttributeMaxDynamicSharedMemorySize,
                         (int)HG_SMEM);

    const dim3 gqkv(QKV / 128, NT / 128);   // (24, 16)
    const dim3 gout(D / 128, NT / 128);     // (8, 16)
    const dim3 gt(32, 32);
    const dim3 gt3(32, 32, 3);
    const dim3 gvt(L / 32, 2, BH);          // (32, 2, 32)
    const dim3 bt(32, 8);
    const int splitBlocks = (NT * D) / (256 * 4);

    split_kernel<<<splitBlocks, 256>>>(x, xh, xl);
    splitT3_kernel<<<gt3, bt>>>(Wq, Wk, Wv, wh3, wl3);
    splitT_kernel<<<gt, bt>>>(Wo, woh, wol);
    hgemm3x<<<gqkv, 256, HG_SMEM>>>(xh, xl, wh3, wl3, pqkv, NT, QKV, D);
    vt_kernel<<<gvt, bt>>>(vth, vtl);
    relq_kernel<<<dim3(L / 32, BH), 256>>>(relk);
    mega_attn_kernel<<<dim3(L / 32, BH), 256, MEGA_SMEM>>>(relv, vth, vtl);
    split_kernel<<<splitBlocks, 256>>>(po, xh, xl);
    hgemm3x<<<gout, 256, HG_SMEM>>>(xh, xl, woh, wol, out, NT, D, D);
}

// round 16
// speedup vs baseline: 1.3978x; 1.0669x over previous
#include <cuda_runtime.h>
#include <cuda_bf16.h>
#include <cstdint>

// ---------------------------------------------------------------------------
// MultiHead2DAttention (Shaw relative positions, T2T variant)
// B=2, L=1024, D=1024, H=16, DH=64, M=64, R=129
// Round 15: (a) K hi/lo bf16 split hoisted out of mega (ksplit_kernel) --
// was recomputed 32x per bh inside the attention CTAs; (b) mega writeout
// emits the bf16 hi/lo split of O directly into g_xh/g_xl, deleting the
// fp32 g_o buffer, one split launch, and 24MB of DRAM traffic.
// Everything else identical to the passing R14 kernel (620.5us).
// ---------------------------------------------------------------------------

namespace {
constexpr int B  = 2;
constexpr int L  = 1024;
constexpr int D  = 1024;
constexpr int H  = 16;
constexpr int DH = 64;
constexpr int MREL = 64;
constexpr int R  = 2 * MREL + 1;   // 129
constexpr int RP = 132;            // padded row stride for relq
constexpr int NT = B * L;          // 2048
constexpr int BH = B * H;          // 32
constexpr int QKV = 3 * D;         // 3072
}

typedef __nv_bfloat16 bf16;
typedef unsigned long long u64;
typedef unsigned int u32;

// Scratch buffers (device globals)
__device__ float g_qkv[(size_t)NT * QKV];
__device__ float g_relq[(size_t)BH * L * RP];

// bf16 split buffers (projection GEMMs; g_xh/g_xl reused for O by mega)
__device__ bf16 g_xh[NT * D];
__device__ bf16 g_xl[NT * D];
__device__ bf16 g_wh3[(size_t)3 * D * D];
__device__ bf16 g_wl3[(size_t)3 * D * D];
__device__ bf16 g_woh[D * D];
__device__ bf16 g_wol[D * D];

// pre-split K: [bh][j][64 d] (row-major, for phase-1 B fragments)
__device__ bf16 g_kth[(size_t)BH * 1024 * 64];
__device__ bf16 g_ktl[(size_t)BH * 1024 * 64];
// pre-transposed + split V: [bh][64 d][1024 j]
__device__ bf16 g_vth[(size_t)BH * 64 * 1024];
__device__ bf16 g_vtl[(size_t)BH * 64 * 1024];

// ---------------------------------------------------------------------------
// helpers
// ---------------------------------------------------------------------------
__device__ __forceinline__ u64 pk2(float x, float y) {
    u64 r;
    asm("mov.b64 %0, {%1, %2};" : "=l"(r) : "f"(x), "f"(y));
    return r;
}
__device__ __forceinline__ u64 dup2(float x) { return pk2(x, x); }
__device__ __forceinline__ u64 ffma2(u64 a, u64 b, u64 c) {
    u64 d;
    asm("fma.rn.f32x2 %0, %1, %2, %3;" : "=l"(d) : "l"(a), "l"(b), "l"(c));
    return d;
}
__device__ __forceinline__ float2 up2(u64 v) {
    float2 f;
    asm("mov.b64 {%0, %1}, %2;" : "=f"(f.x), "=f"(f.y) : "l"(v));
    return f;
}
__device__ __forceinline__ void mma16816(float* c, const u32* a, const u32* b) {
    asm volatile(
        "mma.sync.aligned.m16n8k16.row.col.f32.bf16.bf16.f32 "
        "{%0,%1,%2,%3},{%4,%5,%6,%7},{%8,%9},{%0,%1,%2,%3};"
        : "+f"(c[0]), "+f"(c[1]), "+f"(c[2]), "+f"(c[3])
        : "r"(a[0]), "r"(a[1]), "r"(a[2]), "r"(a[3]), "r"(b[0]), "r"(b[1]));
}
__device__ __forceinline__ void cp16(u32 smem_addr, const void* gptr) {
    asm volatile("cp.async.cg.shared.global [%0], [%1], 16;"
                 :: "r"(smem_addr), "l"(gptr));
}
__device__ __forceinline__ u32 pkh2(float x, float y) {
    __nv_bfloat162 p(__float2bfloat16(x), __float2bfloat16(y));
    return *(u32*)&p;
}
__device__ __forceinline__ u32 pkl2(float x, float y) {
    bf16 hx = __float2bfloat16(x), hy = __float2bfloat16(y);
    __nv_bfloat162 p(__float2bfloat16(x - __bfloat162float(hx)),
                     __float2bfloat16(y - __bfloat162float(hy)));
    return *(u32*)&p;
}

// ---------------------------------------------------------------------------
// split / splitT3 / splitT
// ---------------------------------------------------------------------------
__global__ __launch_bounds__(256) void split_kernel(const float* __restrict__ src,
                                                    bf16* __restrict__ hi,
                                                    bf16* __restrict__ lo) {
    int i = (blockIdx.x * 256 + threadIdx.x) * 4;
    float4 v = *(const float4*)(src + i);
    u32 h0 = pkh2(v.x, v.y), h1 = pkh2(v.z, v.w);
    u32 l0 = pkl2(v.x, v.y), l1 = pkl2(v.z, v.w);
    *(uint2*)(hi + i) = make_uint2(h0, h1);
    *(uint2*)(lo + i) = make_uint2(l0, l1);
}

__global__ void splitT3_kernel(const float* __restrict__ W0,
                               const float* __restrict__ W1,
                               const float* __restrict__ W2,
                               bf16* __restrict__ th, bf16* __restrict__ tl) {
    __shared__ float ts[32][33];
    const int tx = threadIdx.x, ty = threadIdx.y;
    const int n0 = blockIdx.x * 32, k0 = blockIdx.y * 32;
    const int z = blockIdx.z;
    const float* W = (z == 0) ? W0 : (z == 1) ? W1 : W2;
    for (int r = ty; r < 32; r += 8)
        ts[r][tx] = W[(size_t)(k0 + r) * D + n0 + tx];
    __syncthreads();
    const size_t zofs = (size_t)z * D * D;
    for (int r = ty; r < 32; r += 8) {
        float v = ts[tx][r];
        bf16 h = __float2bfloat16(v);
        bf16 l = __float2bfloat16(v - __bfloat162float(h));
        th[zofs + (size_t)(n0 + r) * D + k0 + tx] = h;
        tl[zofs + (size_t)(n0 + r) * D + k0 + tx] = l;
    }
}

__global__ void splitT_kernel(const float* __restrict__ W,
                              bf16* __restrict__ th, bf16* __restrict__ tl) {
    __shared__ float ts[32][33];
    const int tx = threadIdx.x, ty = threadIdx.y;
    const int n0 = blockIdx.x * 32, k0 = blockIdx.y * 32;
    for (int r = ty; r < 32; r += 8)
        ts[r][tx] = W[(size_t)(k0 + r) * D + n0 + tx];
    __syncthreads();
    for (int r = ty; r < 32; r += 8) {
        float v = ts[tx][r];
        bf16 h = __float2bfloat16(v);
        bf16 l = __float2bfloat16(v - __bfloat162float(h));
        th[(size_t)(n0 + r) * D + k0 + tx] = h;
        tl[(size_t)(n0 + r) * D + k0 + tx] = l;
    }
}

// ksplit: K section of g_qkv -> hi/lo bf16 [bh][j][64]  (no transpose)
__global__ __launch_bounds__(256) void ksplit_kernel() {
    int idx = (blockIdx.x * 256 + threadIdx.x) * 4;   // element index
    int d = idx & 63;
    int j = (idx >> 6) & 1023;
    int bh = idx >> 16;
    int b = bh >> 4, h = bh & 15;
    float4 v = *(const float4*)(g_qkv + (size_t)(b * L + j) * QKV + D + h * DH + d);
    *(uint2*)(g_kth + idx) = make_uint2(pkh2(v.x, v.y), pkh2(v.z, v.w));
    *(uint2*)(g_ktl + idx) = make_uint2(pkl2(v.x, v.y), pkl2(v.z, v.w));
}

// vt: V section of g_qkv -> transposed hi/lo bf16 [bh][d][j]
__global__ void vt_kernel(bf16* __restrict__ th, bf16* __restrict__ tl) {
    __shared__ float ts[32][33];
    const int tx = threadIdx.x, ty = threadIdx.y;
    const int j0 = blockIdx.x * 32, d0 = blockIdx.y * 32;
    const int bh = blockIdx.z, b = bh >> 4, h = bh & 15;
    for (int r = ty; r < 32; r += 8)
        ts[r][tx] = g_qkv[(size_t)(b * L + j0 + r) * QKV + 2 * D + h * DH + d0 + tx];
    __syncthreads();
    for (int r = ty; r < 32; r += 8) {
        float v = ts[tx][r];
        bf16 hh = __float2bfloat16(v);
        bf16 ll = __float2bfloat16(v - __bfloat162float(hh));
        size_t o = ((size_t)bh * 64 + d0 + r) * 1024 + j0 + tx;
        th[o] = hh;
        tl[o] = ll;
    }
}

// ---------------------------------------------------------------------------
// hgemm3x: unchanged from R12 (3-stage cp.async ring)
// ---------------------------------------------------------------------------
namespace {
constexpr int HG_STR = 24;
constexpr u32 HG_TB = 128 * HG_STR * 2;
constexpr u32 HG_STAGE_B = 4 * HG_TB;
constexpr u32 HG_SMEM = 3 * HG_STAGE_B;
}

__global__ __launch_bounds__(256) void hgemm3x(const bf16* __restrict__ Ah,
                                               const bf16* __restrict__ Al,
                                               const bf16* __restrict__ Bh,
                                               const bf16* __restrict__ Bl,
                                               float* __restrict__ C,
                                               int Md, int Nd, int Kd) {
    extern __shared__ __align__(16) bf16 hsm[];
    const u32 sbase = (u32)__cvta_generic_to_shared(hsm);

    const int tid = threadIdx.x;
    const int bm = blockIdx.y * 128;
    const int bn = blockIdx.x * 128;
    const int wid = tid >> 5;
    const int lane = tid & 31;
    const int g = lane >> 2;
    const int tg = lane & 3;
    const int wm = (wid & 1) * 64;
    const int wn = (wid >> 1) * 32;

    const int lrow = tid >> 1;
    const int lseg = (tid & 1) * 8;
    const size_t aoff = (size_t)(bm + lrow) * Kd + lseg;
    const size_t boff = (size_t)(bn + lrow) * Kd + lseg;
    const u32 sdst = (u32)(lrow * HG_STR + lseg) * 2;

    float acc[4][4][4];
#pragma unroll
    for (int ma = 0; ma < 4; ++ma)
#pragma unroll
        for (int na = 0; na < 4; ++na)
#pragma unroll
            for (int e = 0; e < 4; ++e) acc[ma][na][e] = 0.0f;

    const int nT = Kd / 16;

    auto stage_tile = [&](int kt, int slot) {
        const u32 o = sbase + (u32)slot * HG_STAGE_B + sdst;
        const size_t ko = (size_t)kt * 16;
        cp16(o + 0 * HG_TB, Ah + aoff + ko);
        cp16(o + 1 * HG_TB, Al + aoff + ko);
        cp16(o + 2 * HG_TB, Bh + boff + ko);
        cp16(o + 3 * HG_TB, Bl + boff + ko);
        asm volatile("cp.async.commit_group;");
    };

    stage_tile(0, 0);
    if (nT > 1) stage_tile(1, 1);

    int slot = 0;
    for (int kt = 0; kt < nT; ++kt) {
        if (kt + 1 < nT) {
            asm volatile("cp.async.wait_group 1;" ::: "memory");
        } else {
            asm volatile("cp.async.wait_group 0;" ::: "memory");
        }
        __syncthreads();
        if (kt + 2 < nT) stage_tile(kt + 2, (slot + 2) % 3);

        const bf16* Abh = hsm + (size_t)slot * (HG_STAGE_B / 2);
        const bf16* Abl = Abh + HG_TB / 2;
        const bf16* Bbh = Abh + 2 * (HG_TB / 2);
        const bf16* Bbl = Abh + 3 * (HG_TB / 2);

        u32 ah[4][4], al[4][4], bh[4][2], bl[4][2];
#pragma unroll
        for (int ma = 0; ma < 4; ++ma) {
            const int r0 = (wm + ma * 16 + g) * HG_STR + 2 * tg;
            const int r1 = r0 + 8 * HG_STR;
            ah[ma][0] = *(const u32*)(Abh + r0);
            ah[ma][1] = *(const u32*)(Abh + r1);
            ah[ma][2] = *(const u32*)(Abh + r0 + 8);
            ah[ma][3] = *(const u32*)(Abh + r1 + 8);
            al[ma][0] = *(const u32*)(Abl + r0);
            al[ma][1] = *(const u32*)(Abl + r1);
            al[ma][2] = *(const u32*)(Abl + r0 + 8);
            al[ma][3] = *(const u32*)(Abl + r1 + 8);
        }
#pragma unroll
        for (int na = 0; na < 4; ++na) {
            const int c0 = (wn + na * 8 + g) * HG_STR + 2 * tg;
            bh[na][0] = *(const u32*)(Bbh + c0);
            bh[na][1] = *(const u32*)(Bbh + c0 + 8);
            bl[na][0] = *(const u32*)(Bbl + c0);
            bl[na][1] = *(const u32*)(Bbl + c0 + 8);
        }

#pragma unroll
        for (int ma = 0; ma < 4; ++ma)
#pragma unroll
            for (int na = 0; na < 4; ++na)
                mma16816(acc[ma][na], ah[ma], bh[na]);
#pragma unroll
        for (int ma = 0; ma < 4; ++ma)
#pragma unroll
            for (int na = 0; na < 4; ++na)
                mma16816(acc[ma][na], ah[ma], bl[na]);
#pragma unroll
        for (int ma = 0; ma < 4; ++ma)
#pragma unroll
            for (int na = 0; na < 4; ++na)
                mma16816(acc[ma][na], al[ma], bh[na]);

        slot = (slot + 1) % 3;
    }

#pragma unroll
    for (int ma = 0; ma < 4; ++ma) {
#pragma unroll
        for (int na = 0; na < 4; ++na) {
            const int r0 = bm + wm + ma * 16 + g;
            const int c = bn + wn + na * 8 + 2 * tg;
            *(float2*)(C + (size_t)r0 * Nd + c) =
                make_float2(acc[ma][na][0], acc[ma][na][1]);
            *(float2*)(C + (size_t)(r0 + 8) * Nd + c) =
                make_float2(acc[ma][na][2], acc[ma][na][3]);
        }
    }
}

// ---------------------------------------------------------------------------
// relq (unchanged)
// ---------------------------------------------------------------------------
__global__ __launch_bounds__(256) void relq_kernel(const float* __restrict__ relk) {
    __shared__ __align__(16) float qsT[64][36];
    __shared__ __align__(16) float tsT[64][132];

    const int tid = threadIdx.x;
    const int bh = blockIdx.y;
    const int b = bh >> 4;
    const int h = bh & 15;
    const int i0 = blockIdx.x * 32;
    const int tx = tid & 31;
    const int ty = tid >> 5;
    const float QS = 0.125f;

    {
        const int rI = tid >> 3;
        const int seg = (tid & 7) * 8;
        const float* qb = g_qkv + (size_t)(b * L + i0 + rI) * QKV + h * DH + seg;
        float4 v0 = *(const float4*)qb;
        float4 v1 = *(const float4*)(qb + 4);
        qsT[seg + 0][rI] = v0.x * QS; qsT[seg + 1][rI] = v0.y * QS;
        qsT[seg + 2][rI] = v0.z * QS; qsT[seg + 3][rI] = v0.w * QS;
        qsT[seg + 4][rI] = v1.x * QS; qsT[seg + 5][rI] = v1.y * QS;
        qsT[seg + 6][rI] = v1.z * QS; qsT[seg + 7][rI] = v1.w * QS;
    }
    for (int e = tid; e < R * 64; e += 256) {
        int r = e >> 6, d = e & 63;
        tsT[d][r] = relk[e];
    }
    __syncthreads();

    u64 acc2[2][4];
#pragma unroll
    for (int p = 0; p < 2; ++p)
#pragma unroll
        for (int j = 0; j < 4; ++j) acc2[p][j] = 0ull;

#pragma unroll 8
    for (int d = 0; d < 64; ++d) {
        const u64* ap = (const u64*)&qsT[d][ty * 4];
        u64 pa0 = ap[0], pa1 = ap[1];
        float4 bv = *(const float4*)&tsT[d][tx * 4];
        u64 pb0 = dup2(bv.x), pb1 = dup2(bv.y), pb2 = dup2(bv.z), pb3 = dup2(bv.w);
        acc2[0][0] = ffma2(pa0, pb0, acc2[0][0]);
        acc2[0][1] = ffma2(pa0, pb1, acc2[0][1]);
        acc2[0][2] = ffma2(pa0, pb2, acc2[0][2]);
        acc2[0][3] = ffma2(pa0, pb3, acc2[0][3]);
        acc2[1][0] = ffma2(pa1, pb0, acc2[1][0]);
        acc2[1][1] = ffma2(pa1, pb1, acc2[1][1]);
        acc2[1][2] = ffma2(pa1, pb2, acc2[1][2]);
        acc2[1][3] = ffma2(pa1, pb3, acc2[1][3]);
    }

#pragma unroll
    for (int p = 0; p < 2; ++p) {
        float2 c0 = up2(acc2[p][0]);
        float2 c1 = up2(acc2[p][1]);
        float2 c2 = up2(acc2[p][2]);
        float2 c3 = up2(acc2[p][3]);
        int gi = i0 + ty * 4 + 2 * p;
        float* o0 = g_relq + ((size_t)bh * L + gi) * RP + tx * 4;
        float* o1 = o0 + RP;
        *(float4*)o0 = make_float4(c0.x, c1.x, c2.x, c3.x);
        *(float4*)o1 = make_float4(c0.y, c1.y, c2.y, c3.y);
    }

    if (tid < 32) {
        float s = 0.0f;
#pragma unroll 8
        for (int d = 0; d < 64; ++d) s += qsT[d][tid] * tsT[d][128];
        g_relq[((size_t)bh * L + i0 + tid) * RP + 128] = s;
    }
}

// ---------------------------------------------------------------------------
// MEGA-fused attention v3: tensor-core logits + AV; K pre-split; O written
// directly as bf16 hi/lo into g_xh/g_xl. 256 threads. grid (L/32, BH).
// ---------------------------------------------------------------------------
namespace {
constexpr int SBS = 1032;
constexpr int KQS = 88;    // K/Q bf16 stride
constexpr int WVS = 136;   // W/V bf16 stride
constexpr int SB_F = 32 * SBS;
constexpr int KV_F = 11264;
constexpr int QW_F = 4352;
constexpr int BW_F = 32 * 132;
constexpr u32 MEGA_SMEM = (SB_F + KV_F + QW_F + BW_F + 32) * 4;
}

__global__ __launch_bounds__(256, 1) void mega_attn_kernel(
        const float* __restrict__ relv) {
    extern __shared__ float fs[];
    float* Sb    = fs;
    float* KVf   = Sb + SB_F;
    float* QWf   = KVf + KV_F;
    float* biasW = QWf + QW_F;
    float* invS  = biasW + BW_F;

    bf16* Kh = (bf16*)KVf;               // [128][88]
    bf16* Kl = Kh + 128 * KQS;
    bf16* Vh = (bf16*)KVf;               // [64][136] (phase 3)
    bf16* Vl = Vh + 64 * WVS;
    float* relvS = KVf;                  // [129][68] (phase 4)
    bf16* Qh = (bf16*)QWf;               // [32][88]
    bf16* Ql = Qh + 32 * KQS;
    bf16* Wh = (bf16*)QWf;               // [32][136] (phase 3)
    bf16* Wl = Wh + 32 * WVS;
    float* Osm = QWf;                    // [32][68] (after phase 3)

    const int tid = threadIdx.x;
    const int bh = blockIdx.y, b = bh >> 4, h = bh & 15;
    const int i0 = blockIdx.x * 32;
    const int w = tid >> 5, lane = tid & 31, g = lane >> 2, tg = lane & 3;

    // ---- stage Q hi/lo ----
    {
        const int rI = tid >> 3, seg = (tid & 7) * 8;
        const float* qb = g_qkv + (size_t)(b * L + i0 + rI) * QKV + h * DH + seg;
        float4 v0 = ((const float4*)qb)[0];
        float4 v1 = ((const float4*)qb)[1];
        uint4 hh = make_uint4(pkh2(v0.x, v0.y), pkh2(v0.z, v0.w),
                              pkh2(v1.x, v1.y), pkh2(v1.z, v1.w));
        uint4 ll = make_uint4(pkl2(v0.x, v0.y), pkl2(v0.z, v0.w),
                              pkl2(v1.x, v1.y), pkl2(v1.z, v1.w));
        *(uint4*)(Qh + rI * KQS + seg) = hh;
        *(uint4*)(Ql + rI * KQS + seg) = ll;
    }
    // ---- stage bias ----
    for (int e = tid; e < 32 * 132; e += 256) {
        int il = e / 132, r = e - il * 132;
        biasW[e] = (r < R) ? g_relq[((size_t)bh * L + i0 + il) * RP + r] : 0.0f;
    }

    // K prefetch (chunk 0) from pre-split global: [bh][j][64] bf16
    const int rJ = tid >> 1, segk = (tid & 1) * 32;   // bf16 element offsets
    const bf16* khg = g_kth + ((size_t)bh * 1024 + rJ) * 64 + segk;
    const bf16* klg = g_ktl + ((size_t)bh * 1024 + rJ) * 64 + segk;
    uint4 kregh[4], kregl[4];
#pragma unroll
    for (int u = 0; u < 4; ++u) {
        kregh[u] = *(const uint4*)(khg + 8 * u);
        kregl[u] = *(const uint4*)(klg + 8 * u);
    }
    __syncthreads();

    // ================= PHASE 1: logits via mma =================
    const int m0 = (w & 1) * 16;
    const int jg = (w >> 1) * 32;
    for (int jc = 0; jc < 8; ++jc) {
#pragma unroll
        for (int u = 0; u < 4; ++u) {
            *(uint4*)(Kh + rJ * KQS + segk + 8 * u) = kregh[u];
            *(uint4*)(Kl + rJ * KQS + segk + 8 * u) = kregl[u];
        }
        __syncthreads();
        if (jc < 7) {
            const int jn = (jc + 1) * 128 * 64;
#pragma unroll
            for (int u = 0; u < 4; ++u) {
                kregh[u] = *(const uint4*)(khg + jn + 8 * u);
                kregl[u] = *(const uint4*)(klg + jn + 8 * u);
            }
        }

        float acc[4][4];
#pragma unroll
        for (int n = 0; n < 4; ++n)
#pragma unroll
            for (int e = 0; e < 4; ++e) acc[n][e] = 0.0f;

#pragma unroll
        for (int kk = 0; kk < 4; ++kk) {
            const int ko = kk * 16 + 2 * tg;
            const bf16* qp = Qh + (m0 + g) * KQS + ko;
            const bf16* qlp = Ql + (m0 + g) * KQS + ko;
            u32 ah[4], al4[4];
            ah[0] = *(const u32*)qp;
            ah[1] = *(const u32*)(qp + 8 * KQS);
            ah[2] = *(const u32*)(qp + 8);
            ah[3] = *(const u32*)(qp + 8 * KQS + 8);
            al4[0] = *(const u32*)qlp;
            al4[1] = *(const u32*)(qlp + 8 * KQS);
            al4[2] = *(const u32*)(qlp + 8);
            al4[3] = *(const u32*)(qlp + 8 * KQS + 8);
            u32 bh_[4][2], bl_[4][2];
#pragma unroll
            for (int n = 0; n < 4; ++n) {
                const bf16* kp = Kh + (jg + n * 8 + g) * KQS + ko;
                const bf16* klp = Kl + (jg + n * 8 + g) * KQS + ko;
                bh_[n][0] = *(const u32*)kp;
                bh_[n][1] = *(const u32*)(kp + 8);
                bl_[n][0] = *(const u32*)klp;
                bl_[n][1] = *(const u32*)(klp + 8);
            }
#pragma unroll
            for (int n = 0; n < 4; ++n) mma16816(acc[n], ah, bh_[n]);
#pragma unroll
            for (int n = 0; n < 4; ++n) mma16816(acc[n], ah, bl_[n]);
#pragma unroll
            for (int n = 0; n < 4; ++n) mma16816(acc[n], al4, bh_[n]);
        }

        const int jb0 = jc * 128 + jg;
#pragma unroll
        for (int n = 0; n < 4; ++n) {
#pragma unroll
            for (int hh = 0; hh < 2; ++hh) {
                const int il = m0 + g + 8 * hh;
                const int gi = i0 + il;
                const int jj = jb0 + n * 8 + 2 * tg;
                const float* brow = biasW + il * 132;
                int r0 = min(max(jj - gi, -MREL), MREL) + MREL;
                int r1 = min(max(jj + 1 - gi, -MREL), MREL) + MREL;
                float2 o;
                o.x = acc[n][2 * hh] * 0.125f + brow[r0];
                o.y = acc[n][2 * hh + 1] * 0.125f + brow[r1];
                *(float2*)&Sb[il * SBS + jj] = o;
            }
        }
        __syncthreads();
    }

    // ================= PHASE 2: softmax + raw wsum =================
    {
        const int row = tid >> 3;
        const int ts = tid & 7;
        const int gi = i0 + row;
        float* srow = Sb + row * SBS;

        float m = -3.0e38f;
#pragma unroll 8
        for (int c = 0; c < 32; ++c) {
            float4 v = *(const float4*)&srow[ts * 4 + c * 32];
            m = fmaxf(m, fmaxf(fmaxf(v.x, v.y), fmaxf(v.z, v.w)));
        }
#pragma unroll
        for (int o = 4; o > 0; o >>= 1)
            m = fmaxf(m, __shfl_xor_sync(0xffffffffu, m, o));

        float s = 0.0f;
#pragma unroll 8
        for (int c = 0; c < 32; ++c) {
            float4 v = *(float4*)&srow[ts * 4 + c * 32];
            v.x = __expf(v.x - m); v.y = __expf(v.y - m);
            v.z = __expf(v.z - m); v.w = __expf(v.w - m);
            *(float4*)&srow[ts * 4 + c * 32] = v;
            s += v.x + v.y + v.z + v.w;
        }
#pragma unroll
        for (int o = 4; o > 0; o >>= 1) s += __shfl_xor_sync(0xffffffffu, s, o);
        if (ts == 0) invS[row] = 1.0f / s;

        float hp = 0.0f, tp = 0.0f;
        for (int j = ts; j <= gi - MREL; j += 8) hp += srow[j];
        for (int j = gi + MREL + ts; j < L; j += 8) tp += srow[j];
#pragma unroll
        for (int o = 4; o > 0; o >>= 1) {
            hp += __shfl_xor_sync(0xffffffffu, hp, o);
            tp += __shfl_xor_sync(0xffffffffu, tp, o);
        }
        __syncthreads();

        float* wrow = biasW + row * 132;
#pragma unroll
        for (int k = 0; k < 16; ++k) {
            int r = 1 + ts * 16 + k;
            if (r < 128) {
                int j = gi + r - 64;
                wrow[r] = (j >= 0 && j < L) ? srow[j] : 0.0f;
            }
        }
        if (ts == 0) {
            wrow[0] = hp;
            wrow[128] = tp;
        }
    }

    // ================= PHASE 3: O = exp @ V via mma =================
    const int dd = tid >> 2, js = (tid & 3) * 32;
    const bf16* vhg = g_vth + ((size_t)bh * 64 + dd) * 1024 + js;
    const bf16* vlg = g_vtl + ((size_t)bh * 64 + dd) * 1024 + js;
    uint4 vph[4], vpl[4];
#pragma unroll
    for (int u = 0; u < 4; ++u) {
        vph[u] = *(const uint4*)(vhg + 8 * u);
        vpl[u] = *(const uint4*)(vlg + 8 * u);
    }
    __syncthreads();

    float acc3[2][4];
#pragma unroll
    for (int n = 0; n < 2; ++n)
#pragma unroll
        for (int e = 0; e < 4; ++e) acc3[n][e] = 0.0f;
    const int dg = (w >> 1) * 16;

    for (int jc = 0; jc < 8; ++jc) {
#pragma unroll
        for (int u = 0; u < 4; ++u) {
            *(uint4*)(Vh + dd * WVS + js + 8 * u) = vph[u];
            *(uint4*)(Vl + dd * WVS + js + 8 * u) = vpl[u];
        }
        {
            const int rr = tid & 31, cs = (tid >> 5) * 16;
            const float* sp = Sb + rr * SBS + jc * 128 + cs;
            float4 x0 = ((const float4*)sp)[0];
            float4 x1 = ((const float4*)sp)[1];
            float4 x2 = ((const float4*)sp)[2];
            float4 x3 = ((const float4*)sp)[3];
            *(uint4*)(Wh + rr * WVS + cs) = make_uint4(
                pkh2(x0.x, x0.y), pkh2(x0.z, x0.w), pkh2(x1.x, x1.y), pkh2(x1.z, x1.w));
            *(uint4*)(Wh + rr * WVS + cs + 8) = make_uint4(
                pkh2(x2.x, x2.y), pkh2(x2.z, x2.w), pkh2(x3.x, x3.y), pkh2(x3.z, x3.w));
            *(uint4*)(Wl + rr * WVS + cs) = make_uint4(
                pkl2(x0.x, x0.y), pkl2(x0.z, x0.w), pkl2(x1.x, x1.y), pkl2(x1.z, x1.w));
            *(uint4*)(Wl + rr * WVS + cs + 8) = make_uint4(
                pkl2(x2.x, x2.y), pkl2(x2.z, x2.w), pkl2(x3.x, x3.y), pkl2(x3.z, x3.w));
        }
        __syncthreads();
        if (jc < 7) {
            const int jn = (jc + 1) * 128;
#pragma unroll
            for (int u = 0; u < 4; ++u) {
                vph[u] = *(const uint4*)(vhg + jn + 8 * u);
                vpl[u] = *(const uint4*)(vlg + jn + 8 * u);
            }
        }

#pragma unroll
        for (int kk = 0; kk < 8; ++kk) {
            const int ko = kk * 16 + 2 * tg;
            const bf16* wp = Wh + (m0 + g) * WVS + ko;
            const bf16* wlp = Wl + (m0 + g) * WVS + ko;
            u32 ah[4], al4[4];
            ah[0] = *(const u32*)wp;
            ah[1] = *(const u32*)(wp + 8 * WVS);
            ah[2] = *(const u32*)(wp + 8);
            ah[3] = *(const u32*)(wp + 8 * WVS + 8);
            al4[0] = *(const u32*)wlp;
            al4[1] = *(const u32*)(wlp + 8 * WVS);
            al4[2] = *(const u32*)(wlp + 8);
            al4[3] = *(const u32*)(wlp + 8 * WVS + 8);
            u32 bh_[2][2], bl_[2][2];
#pragma unroll
            for (int n = 0; n < 2; ++n) {
                const bf16* vp = Vh + (dg + n * 8 + g) * WVS + ko;
                const bf16* vlp = Vl + (dg + n * 8 + g) * WVS + ko;
                bh_[n][0] = *(const u32*)vp;
                bh_[n][1] = *(const u32*)(vp + 8);
                bl_[n][0] = *(const u32*)vlp;
                bl_[n][1] = *(const u32*)(vlp + 8);
            }
#pragma unroll
            for (int n = 0; n < 2; ++n) mma16816(acc3[n], ah, bh_[n]);
#pragma unroll
            for (int n = 0; n < 2; ++n) mma16816(acc3[n], ah, bl_[n]);
#pragma unroll
            for (int n = 0; n < 2; ++n) mma16816(acc3[n], al4, bh_[n]);
        }
        __syncthreads();
    }

    // write O accumulators to smem; stage relv
#pragma unroll
    for (int n = 0; n < 2; ++n) {
#pragma unroll
        for (int hh = 0; hh < 2; ++hh) {
            const int il = m0 + g + 8 * hh;
            *(float2*)&Osm[il * 68 + dg + n * 8 + 2 * tg] =
                make_float2(acc3[n][2 * hh], acc3[n][2 * hh + 1]);
        }
    }
    for (int e = tid; e < R * 64; e += 256) {
        relvS[(e >> 6) * 68 + (e & 63)] = relv[e];
    }
    __syncthreads();

    // ================= PHASE 4: rel_v + writeout (bf16 hi/lo) =================
    {
        const int ii = tid & 31, dg8 = (tid >> 5) * 8;
        const float* wrow = biasW + ii * 132;
        u64 a4[4] = {0ull, 0ull, 0ull, 0ull};
        for (int r = 0; r <= 128; ++r) {
            u64 wd = dup2(wrow[r]);
            const float* vr = relvS + r * 68 + dg8;
            a4[0] = ffma2(wd, *(const u64*)(vr + 0), a4[0]);
            a4[1] = ffma2(wd, *(const u64*)(vr + 2), a4[1]);
            a4[2] = ffma2(wd, *(const u64*)(vr + 4), a4[2]);
            a4[3] = ffma2(wd, *(const u64*)(vr + 6), a4[3]);
        }
        const float iv = invS[ii];
        const float* op = Osm + ii * 68 + dg8;
        float2 p0 = up2(a4[0]), p1 = up2(a4[1]), p2 = up2(a4[2]), p3 = up2(a4[3]);
        float o0 = (op[0] + p0.x) * iv, o1 = (op[1] + p0.y) * iv;
        float o2 = (op[2] + p1.x) * iv, o3 = (op[3] + p1.y) * iv;
        float o4 = (op[4] + p2.x) * iv, o5 = (op[5] + p2.y) * iv;
        float o6 = (op[6] + p3.x) * iv, o7 = (op[7] + p3.y) * iv;
        const size_t ob = (size_t)(b * L + i0 + ii) * D + h * DH + dg8;
        *(uint4*)(g_xh + ob) = make_uint4(pkh2(o0, o1), pkh2(o2, o3),
                                          pkh2(o4, o5), pkh2(o6, o7));
        *(uint4*)(g_xl + ob) = make_uint4(pkl2(o0, o1), pkl2(o2, o3),
                                          pkl2(o4, o5), pkl2(o6, o7));
    }
}

// ---------------------------------------------------------------------------
// Launch
// ---------------------------------------------------------------------------
extern "C" void kernel_launch(void* const* d_in, const int* in_sizes, int n_in,
                              void* d_out, int out_size) {
    const float* x    = (const float*)d_in[0];
    const float* Wq   = (const float*)d_in[1];
    const float* Wk   = (const float*)d_in[2];
    const float* Wv   = (const float*)d_in[3];
    const float* Wo   = (const float*)d_in[4];
    const float* relk = (const float*)d_in[5];
    const float* relv = (const float*)d_in[6];
    float* out = (float*)d_out;

    float* pqkv;
    cudaGetSymbolAddress((void**)&pqkv, g_qkv);
    bf16 *xh, *xl, *wh3, *wl3, *woh, *wol, *vth, *vtl;
    cudaGetSymbolAddress((void**)&xh, g_xh);
    cudaGetSymbolAddress((void**)&xl, g_xl);
    cudaGetSymbolAddress((void**)&wh3, g_wh3);
    cudaGetSymbolAddress((void**)&wl3, g_wl3);
    cudaGetSymbolAddress((void**)&woh, g_woh);
    cudaGetSymbolAddress((void**)&wol, g_wol);
    cudaGetSymbolAddress((void**)&vth, g_vth);
    cudaGetSymbolAddress((void**)&vtl, g_vtl);

    cudaFuncSetAttribute(mega_attn_kernel,
                         cudaFuncAttributeMaxDynamicSharedMemorySize,
                         (int)MEGA_SMEM);
    cudaFuncSetAttribute(hgemm3x,
                         cudaFuncAttributeMaxDynamicSharedMemorySize,
                         (int)HG_SMEM);

    const dim3 gqkv(QKV / 128, NT / 128);   // (24, 16)
    const dim3 gout(D / 128, NT / 128);     // (8, 16)
    const dim3 gt(32, 32);
    const dim3 gt3(32, 32, 3);
    const dim3 gvt(L / 32, 2, BH);          // (32, 2, 32)
    const dim3 bt(32, 8);
    const int splitBlocks = (NT * D) / (256 * 4);
    const int ksplitBlocks = (BH * 1024 * 64) / (256 * 4);   // 2048

    split_kernel<<<splitBlocks, 256>>>(x, xh, xl);
    splitT3_kernel<<<gt3, bt>>>(Wq, Wk, Wv, wh3, wl3);
    splitT_kernel<<<gt, bt>>>(Wo, woh, wol);
    hgemm3x<<<gqkv, 256, HG_SMEM>>>(xh, xl, wh3, wl3, pqkv, NT, QKV, D);
    ksplit_kernel<<<ksplitBlocks, 256>>>();
    vt_kernel<<<gvt, bt>>>(vth, vtl);
    relq_kernel<<<dim3(L / 32, BH), 256>>>(relk);
    mega_attn_kernel<<<dim3(L / 32, BH), 256, MEGA_SMEM>>>(relv);
    // mega wrote O's bf16 split directly into g_xh/g_xl:
    hgemm3x<<<gout, 256, HG_SMEM>>>(xh, xl, woh, wol, out, NT, D, D);
}

// round 17
// speedup vs baseline: 1.4374x; 1.0283x over previous
#include <cuda_runtime.h>
#include <cuda_bf16.h>
#include <cstdint>

// ---------------------------------------------------------------------------
// MultiHead2DAttention (Shaw relative positions, T2T variant)
// B=2, L=1024, D=1024, H=16, DH=64, M=64, R=129
// Round 16: mega_attn_kernel 256 -> 512 threads (16 warps). The MMA version
// is latency-bound at 2 warps/SMSP (T_CTA ~65K cyc vs ~14K issue / ~12K
// tensor floor); doubling warps halves exposed LDS/MMA/MUFU latency.
// Warp tiles: phase1 16x16, phase3 16x8. Smem & arithmetic unchanged.
// Everything else identical to passing R15 (581.6us).
// ---------------------------------------------------------------------------

namespace {
constexpr int B  = 2;
constexpr int L  = 1024;
constexpr int D  = 1024;
constexpr int H  = 16;
constexpr int DH = 64;
constexpr int MREL = 64;
constexpr int R  = 2 * MREL + 1;   // 129
constexpr int RP = 132;            // padded row stride for relq
constexpr int NT = B * L;          // 2048
constexpr int BH = B * H;          // 32
constexpr int QKV = 3 * D;         // 3072
}

typedef __nv_bfloat16 bf16;
typedef unsigned long long u64;
typedef unsigned int u32;

// Scratch buffers (device globals)
__device__ float g_qkv[(size_t)NT * QKV];
__device__ float g_relq[(size_t)BH * L * RP];

// bf16 split buffers (projection GEMMs; g_xh/g_xl reused for O by mega)
__device__ bf16 g_xh[NT * D];
__device__ bf16 g_xl[NT * D];
__device__ bf16 g_wh3[(size_t)3 * D * D];
__device__ bf16 g_wl3[(size_t)3 * D * D];
__device__ bf16 g_woh[D * D];
__device__ bf16 g_wol[D * D];

// pre-split K: [bh][j][64 d]
__device__ bf16 g_kth[(size_t)BH * 1024 * 64];
__device__ bf16 g_ktl[(size_t)BH * 1024 * 64];
// pre-transposed + split V: [bh][64 d][1024 j]
__device__ bf16 g_vth[(size_t)BH * 64 * 1024];
__device__ bf16 g_vtl[(size_t)BH * 64 * 1024];

// ---------------------------------------------------------------------------
// helpers
// ---------------------------------------------------------------------------
__device__ __forceinline__ u64 pk2(float x, float y) {
    u64 r;
    asm("mov.b64 %0, {%1, %2};" : "=l"(r) : "f"(x), "f"(y));
    return r;
}
__device__ __forceinline__ u64 dup2(float x) { return pk2(x, x); }
__device__ __forceinline__ u64 ffma2(u64 a, u64 b, u64 c) {
    u64 d;
    asm("fma.rn.f32x2 %0, %1, %2, %3;" : "=l"(d) : "l"(a), "l"(b), "l"(c));
    return d;
}
__device__ __forceinline__ float2 up2(u64 v) {
    float2 f;
    asm("mov.b64 {%0, %1}, %2;" : "=f"(f.x), "=f"(f.y) : "l"(v));
    return f;
}
__device__ __forceinline__ void mma16816(float* c, const u32* a, const u32* b) {
    asm volatile(
        "mma.sync.aligned.m16n8k16.row.col.f32.bf16.bf16.f32 "
        "{%0,%1,%2,%3},{%4,%5,%6,%7},{%8,%9},{%0,%1,%2,%3};"
        : "+f"(c[0]), "+f"(c[1]), "+f"(c[2]), "+f"(c[3])
        : "r"(a[0]), "r"(a[1]), "r"(a[2]), "r"(a[3]), "r"(b[0]), "r"(b[1]));
}
__device__ __forceinline__ void cp16(u32 smem_addr, const void* gptr) {
    asm volatile("cp.async.cg.shared.global [%0], [%1], 16;"
                 :: "r"(smem_addr), "l"(gptr));
}
__device__ __forceinline__ u32 pkh2(float x, float y) {
    __nv_bfloat162 p(__float2bfloat16(x), __float2bfloat16(y));
    return *(u32*)&p;
}
__device__ __forceinline__ u32 pkl2(float x, float y) {
    bf16 hx = __float2bfloat16(x), hy = __float2bfloat16(y);
    __nv_bfloat162 p(__float2bfloat16(x - __bfloat162float(hx)),
                     __float2bfloat16(y - __bfloat162float(hy)));
    return *(u32*)&p;
}

// ---------------------------------------------------------------------------
// split / splitT3 / splitT / ksplit / vt  (unchanged)
// ---------------------------------------------------------------------------
__global__ __launch_bounds__(256) void split_kernel(const float* __restrict__ src,
                                                    bf16* __restrict__ hi,
                                                    bf16* __restrict__ lo) {
    int i = (blockIdx.x * 256 + threadIdx.x) * 4;
    float4 v = *(const float4*)(src + i);
    u32 h0 = pkh2(v.x, v.y), h1 = pkh2(v.z, v.w);
    u32 l0 = pkl2(v.x, v.y), l1 = pkl2(v.z, v.w);
    *(uint2*)(hi + i) = make_uint2(h0, h1);
    *(uint2*)(lo + i) = make_uint2(l0, l1);
}

__global__ void splitT3_kernel(const float* __restrict__ W0,
                               const float* __restrict__ W1,
                               const float* __restrict__ W2,
                               bf16* __restrict__ th, bf16* __restrict__ tl) {
    __shared__ float ts[32][33];
    const int tx = threadIdx.x, ty = threadIdx.y;
    const int n0 = blockIdx.x * 32, k0 = blockIdx.y * 32;
    const int z = blockIdx.z;
    const float* W = (z == 0) ? W0 : (z == 1) ? W1 : W2;
    for (int r = ty; r < 32; r += 8)
        ts[r][tx] = W[(size_t)(k0 + r) * D + n0 + tx];
    __syncthreads();
    const size_t zofs = (size_t)z * D * D;
    for (int r = ty; r < 32; r += 8) {
        float v = ts[tx][r];
        bf16 h = __float2bfloat16(v);
        bf16 l = __float2bfloat16(v - __bfloat162float(h));
        th[zofs + (size_t)(n0 + r) * D + k0 + tx] = h;
        tl[zofs + (size_t)(n0 + r) * D + k0 + tx] = l;
    }
}

__global__ void splitT_kernel(const float* __restrict__ W,
                              bf16* __restrict__ th, bf16* __restrict__ tl) {
    __shared__ float ts[32][33];
    const int tx = threadIdx.x, ty = threadIdx.y;
    const int n0 = blockIdx.x * 32, k0 = blockIdx.y * 32;
    for (int r = ty; r < 32; r += 8)
        ts[r][tx] = W[(size_t)(k0 + r) * D + n0 + tx];
    __syncthreads();
    for (int r = ty; r < 32; r += 8) {
        float v = ts[tx][r];
        bf16 h = __float2bfloat16(v);
        bf16 l = __float2bfloat16(v - __bfloat162float(h));
        th[(size_t)(n0 + r) * D + k0 + tx] = h;
        tl[(size_t)(n0 + r) * D + k0 + tx] = l;
    }
}

__global__ __launch_bounds__(256) void ksplit_kernel() {
    int idx = (blockIdx.x * 256 + threadIdx.x) * 4;
    int d = idx & 63;
    int j = (idx >> 6) & 1023;
    int bh = idx >> 16;
    int b = bh >> 4, h = bh & 15;
    float4 v = *(const float4*)(g_qkv + (size_t)(b * L + j) * QKV + D + h * DH + d);
    *(uint2*)(g_kth + idx) = make_uint2(pkh2(v.x, v.y), pkh2(v.z, v.w));
    *(uint2*)(g_ktl + idx) = make_uint2(pkl2(v.x, v.y), pkl2(v.z, v.w));
}

__global__ void vt_kernel(bf16* __restrict__ th, bf16* __restrict__ tl) {
    __shared__ float ts[32][33];
    const int tx = threadIdx.x, ty = threadIdx.y;
    const int j0 = blockIdx.x * 32, d0 = blockIdx.y * 32;
    const int bh = blockIdx.z, b = bh >> 4, h = bh & 15;
    for (int r = ty; r < 32; r += 8)
        ts[r][tx] = g_qkv[(size_t)(b * L + j0 + r) * QKV + 2 * D + h * DH + d0 + tx];
    __syncthreads();
    for (int r = ty; r < 32; r += 8) {
        float v = ts[tx][r];
        bf16 hh = __float2bfloat16(v);
        bf16 ll = __float2bfloat16(v - __bfloat162float(hh));
        size_t o = ((size_t)bh * 64 + d0 + r) * 1024 + j0 + tx;
        th[o] = hh;
        tl[o] = ll;
    }
}

// ---------------------------------------------------------------------------
// hgemm3x (unchanged)
// ---------------------------------------------------------------------------
namespace {
constexpr int HG_STR = 24;
constexpr u32 HG_TB = 128 * HG_STR * 2;
constexpr u32 HG_STAGE_B = 4 * HG_TB;
constexpr u32 HG_SMEM = 3 * HG_STAGE_B;
}

__global__ __launch_bounds__(256) void hgemm3x(const bf16* __restrict__ Ah,
                                               const bf16* __restrict__ Al,
                                               const bf16* __restrict__ Bh,
                                               const bf16* __restrict__ Bl,
                                               float* __restrict__ C,
                                               int Md, int Nd, int Kd) {
    extern __shared__ __align__(16) bf16 hsm[];
    const u32 sbase = (u32)__cvta_generic_to_shared(hsm);

    const int tid = threadIdx.x;
    const int bm = blockIdx.y * 128;
    const int bn = blockIdx.x * 128;
    const int wid = tid >> 5;
    const int lane = tid & 31;
    const int g = lane >> 2;
    const int tg = lane & 3;
    const int wm = (wid & 1) * 64;
    const int wn = (wid >> 1) * 32;

    const int lrow = tid >> 1;
    const int lseg = (tid & 1) * 8;
    const size_t aoff = (size_t)(bm + lrow) * Kd + lseg;
    const size_t boff = (size_t)(bn + lrow) * Kd + lseg;
    const u32 sdst = (u32)(lrow * HG_STR + lseg) * 2;

    float acc[4][4][4];
#pragma unroll
    for (int ma = 0; ma < 4; ++ma)
#pragma unroll
        for (int na = 0; na < 4; ++na)
#pragma unroll
            for (int e = 0; e < 4; ++e) acc[ma][na][e] = 0.0f;

    const int nT = Kd / 16;

    auto stage_tile = [&](int kt, int slot) {
        const u32 o = sbase + (u32)slot * HG_STAGE_B + sdst;
        const size_t ko = (size_t)kt * 16;
        cp16(o + 0 * HG_TB, Ah + aoff + ko);
        cp16(o + 1 * HG_TB, Al + aoff + ko);
        cp16(o + 2 * HG_TB, Bh + boff + ko);
        cp16(o + 3 * HG_TB, Bl + boff + ko);
        asm volatile("cp.async.commit_group;");
    };

    stage_tile(0, 0);
    if (nT > 1) stage_tile(1, 1);

    int slot = 0;
    for (int kt = 0; kt < nT; ++kt) {
        if (kt + 1 < nT) {
            asm volatile("cp.async.wait_group 1;" ::: "memory");
        } else {
            asm volatile("cp.async.wait_group 0;" ::: "memory");
        }
        __syncthreads();
        if (kt + 2 < nT) stage_tile(kt + 2, (slot + 2) % 3);

        const bf16* Abh = hsm + (size_t)slot * (HG_STAGE_B / 2);
        const bf16* Abl = Abh + HG_TB / 2;
        const bf16* Bbh = Abh + 2 * (HG_TB / 2);
        const bf16* Bbl = Abh + 3 * (HG_TB / 2);

        u32 ah[4][4], al[4][4], bh[4][2], bl[4][2];
#pragma unroll
        for (int ma = 0; ma < 4; ++ma) {
            const int r0 = (wm + ma * 16 + g) * HG_STR + 2 * tg;
            const int r1 = r0 + 8 * HG_STR;
            ah[ma][0] = *(const u32*)(Abh + r0);
            ah[ma][1] = *(const u32*)(Abh + r1);
            ah[ma][2] = *(const u32*)(Abh + r0 + 8);
            ah[ma][3] = *(const u32*)(Abh + r1 + 8);
            al[ma][0] = *(const u32*)(Abl + r0);
            al[ma][1] = *(const u32*)(Abl + r1);
            al[ma][2] = *(const u32*)(Abl + r0 + 8);
            al[ma][3] = *(const u32*)(Abl + r1 + 8);
        }
#pragma unroll
        for (int na = 0; na < 4; ++na) {
            const int c0 = (wn + na * 8 + g) * HG_STR + 2 * tg;
            bh[na][0] = *(const u32*)(Bbh + c0);
            bh[na][1] = *(const u32*)(Bbh + c0 + 8);
            bl[na][0] = *(const u32*)(Bbl + c0);
            bl[na][1] = *(const u32*)(Bbl + c0 + 8);
        }

#pragma unroll
        for (int ma = 0; ma < 4; ++ma)
#pragma unroll
            for (int na = 0; na < 4; ++na)
                mma16816(acc[ma][na], ah[ma], bh[na]);
#pragma unroll
        for (int ma = 0; ma < 4; ++ma)
#pragma unroll
            for (int na = 0; na < 4; ++na)
                mma16816(acc[ma][na], ah[ma], bl[na]);
#pragma unroll
        for (int ma = 0; ma < 4; ++ma)
#pragma unroll
            for (int na = 0; na < 4; ++na)
                mma16816(acc[ma][na], al[ma], bh[na]);

        slot = (slot + 1) % 3;
    }

#pragma unroll
    for (int ma = 0; ma < 4; ++ma) {
#pragma unroll
        for (int na = 0; na < 4; ++na) {
            const int r0 = bm + wm + ma * 16 + g;
            const int c = bn + wn + na * 8 + 2 * tg;
            *(float2*)(C + (size_t)r0 * Nd + c) =
                make_float2(acc[ma][na][0], acc[ma][na][1]);
            *(float2*)(C + (size_t)(r0 + 8) * Nd + c) =
                make_float2(acc[ma][na][2], acc[ma][na][3]);
        }
    }
}

// ---------------------------------------------------------------------------
// relq (unchanged)
// ---------------------------------------------------------------------------
__global__ __launch_bounds__(256) void relq_kernel(const float* __restrict__ relk) {
    __shared__ __align__(16) float qsT[64][36];
    __shared__ __align__(16) float tsT[64][132];

    const int tid = threadIdx.x;
    const int bh = blockIdx.y;
    const int b = bh >> 4;
    const int h = bh & 15;
    const int i0 = blockIdx.x * 32;
    const int tx = tid & 31;
    const int ty = tid >> 5;
    const float QS = 0.125f;

    {
        const int rI = tid >> 3;
        const int seg = (tid & 7) * 8;
        const float* qb = g_qkv + (size_t)(b * L + i0 + rI) * QKV + h * DH + seg;
        float4 v0 = *(const float4*)qb;
        float4 v1 = *(const float4*)(qb + 4);
        qsT[seg + 0][rI] = v0.x * QS; qsT[seg + 1][rI] = v0.y * QS;
        qsT[seg + 2][rI] = v0.z * QS; qsT[seg + 3][rI] = v0.w * QS;
        qsT[seg + 4][rI] = v1.x * QS; qsT[seg + 5][rI] = v1.y * QS;
        qsT[seg + 6][rI] = v1.z * QS; qsT[seg + 7][rI] = v1.w * QS;
    }
    for (int e = tid; e < R * 64; e += 256) {
        int r = e >> 6, d = e & 63;
        tsT[d][r] = relk[e];
    }
    __syncthreads();

    u64 acc2[2][4];
#pragma unroll
    for (int p = 0; p < 2; ++p)
#pragma unroll
        for (int j = 0; j < 4; ++j) acc2[p][j] = 0ull;

#pragma unroll 8
    for (int d = 0; d < 64; ++d) {
        const u64* ap = (const u64*)&qsT[d][ty * 4];
        u64 pa0 = ap[0], pa1 = ap[1];
        float4 bv = *(const float4*)&tsT[d][tx * 4];
        u64 pb0 = dup2(bv.x), pb1 = dup2(bv.y), pb2 = dup2(bv.z), pb3 = dup2(bv.w);
        acc2[0][0] = ffma2(pa0, pb0, acc2[0][0]);
        acc2[0][1] = ffma2(pa0, pb1, acc2[0][1]);
        acc2[0][2] = ffma2(pa0, pb2, acc2[0][2]);
        acc2[0][3] = ffma2(pa0, pb3, acc2[0][3]);
        acc2[1][0] = ffma2(pa1, pb0, acc2[1][0]);
        acc2[1][1] = ffma2(pa1, pb1, acc2[1][1]);
        acc2[1][2] = ffma2(pa1, pb2, acc2[1][2]);
        acc2[1][3] = ffma2(pa1, pb3, acc2[1][3]);
    }

#pragma unroll
    for (int p = 0; p < 2; ++p) {
        float2 c0 = up2(acc2[p][0]);
        float2 c1 = up2(acc2[p][1]);
        float2 c2 = up2(acc2[p][2]);
        float2 c3 = up2(acc2[p][3]);
        int gi = i0 + ty * 4 + 2 * p;
        float* o0 = g_relq + ((size_t)bh * L + gi) * RP + tx * 4;
        float* o1 = o0 + RP;
        *(float4*)o0 = make_float4(c0.x, c1.x, c2.x, c3.x);
        *(float4*)o1 = make_float4(c0.y, c1.y, c2.y, c3.y);
    }

    if (tid < 32) {
        float s = 0.0f;
#pragma unroll 8
        for (int d = 0; d < 64; ++d) s += qsT[d][tid] * tsT[d][128];
        g_relq[((size_t)bh * L + i0 + tid) * RP + 128] = s;
    }
}

// ---------------------------------------------------------------------------
// MEGA-fused attention v4: 512 threads (16 warps), tensor-core logits + AV.
// Warp tiles: phase1 16x16, phase3 16x8. grid (L/32, BH).
// ---------------------------------------------------------------------------
namespace {
constexpr int SBS = 1032;
constexpr int KQS = 88;    // K/Q bf16 stride
constexpr int WVS = 136;   // W/V bf16 stride
constexpr int SB_F = 32 * SBS;
constexpr int KV_F = 11264;
constexpr int QW_F = 4352;
constexpr int BW_F = 32 * 132;
constexpr u32 MEGA_SMEM = (SB_F + KV_F + QW_F + BW_F + 32) * 4;
}

__global__ __launch_bounds__(512, 1) void mega_attn_kernel(
        const float* __restrict__ relv) {
    extern __shared__ float fs[];
    float* Sb    = fs;
    float* KVf   = Sb + SB_F;
    float* QWf   = KVf + KV_F;
    float* biasW = QWf + QW_F;
    float* invS  = biasW + BW_F;

    bf16* Kh = (bf16*)KVf;               // [128][88]
    bf16* Kl = Kh + 128 * KQS;
    bf16* Vh = (bf16*)KVf;               // [64][136] (phase 3)
    bf16* Vl = Vh + 64 * WVS;
    float* relvS = KVf;                  // [129][68] (phase 4)
    bf16* Qh = (bf16*)QWf;               // [32][88]
    bf16* Ql = Qh + 32 * KQS;
    bf16* Wh = (bf16*)QWf;               // [32][136] (phase 3)
    bf16* Wl = Wh + 32 * WVS;
    float* Osm = QWf;                    // [32][68] (after phase 3)

    const int tid = threadIdx.x;
    const int bh = blockIdx.y, b = bh >> 4, h = bh & 15;
    const int i0 = blockIdx.x * 32;
    const int w = tid >> 5, lane = tid & 31, g = lane >> 2, tg = lane & 3;

    // ---- stage Q hi/lo (512 threads: 1 float4 each) ----
    {
        const int rI = tid >> 4, seg = (tid & 15) * 4;
        const float* qb = g_qkv + (size_t)(b * L + i0 + rI) * QKV + h * DH + seg;
        float4 v = *(const float4*)qb;
        *(uint2*)(Qh + rI * KQS + seg) = make_uint2(pkh2(v.x, v.y), pkh2(v.z, v.w));
        *(uint2*)(Ql + rI * KQS + seg) = make_uint2(pkl2(v.x, v.y), pkl2(v.z, v.w));
    }
    // ---- stage bias ----
    for (int e = tid; e < 32 * 132; e += 512) {
        int il = e / 132, r = e - il * 132;
        biasW[e] = (r < R) ? g_relq[((size_t)bh * L + i0 + il) * RP + r] : 0.0f;
    }

    // K prefetch (chunk 0): 512 threads, 4 per row, 16 bf16 each
    const int rJ = tid >> 2, segk = (tid & 3) * 16;
    const bf16* khg = g_kth + ((size_t)bh * 1024 + rJ) * 64 + segk;
    const bf16* klg = g_ktl + ((size_t)bh * 1024 + rJ) * 64 + segk;
    uint4 kregh[2], kregl[2];
#pragma unroll
    for (int u = 0; u < 2; ++u) {
        kregh[u] = *(const uint4*)(khg + 8 * u);
        kregl[u] = *(const uint4*)(klg + 8 * u);
    }
    __syncthreads();

    // ================= PHASE 1: logits via mma (warp tile 16x16) =========
    const int m0 = (w & 1) * 16;
    const int jg = (w >> 1) * 16;           // 8 j-groups of 16
    for (int jc = 0; jc < 8; ++jc) {
#pragma unroll
        for (int u = 0; u < 2; ++u) {
            *(uint4*)(Kh + rJ * KQS + segk + 8 * u) = kregh[u];
            *(uint4*)(Kl + rJ * KQS + segk + 8 * u) = kregl[u];
        }
        __syncthreads();
        if (jc < 7) {
            const int jn = (jc + 1) * 128 * 64;
#pragma unroll
            for (int u = 0; u < 2; ++u) {
                kregh[u] = *(const uint4*)(khg + jn + 8 * u);
                kregl[u] = *(const uint4*)(klg + jn + 8 * u);
            }
        }

        float acc[2][4];
#pragma unroll
        for (int n = 0; n < 2; ++n)
#pragma unroll
            for (int e = 0; e < 4; ++e) acc[n][e] = 0.0f;

#pragma unroll
        for (int kk = 0; kk < 4; ++kk) {
            const int ko = kk * 16 + 2 * tg;
            const bf16* qp = Qh + (m0 + g) * KQS + ko;
            const bf16* qlp = Ql + (m0 + g) * KQS + ko;
            u32 ah[4], al4[4];
            ah[0] = *(const u32*)qp;
            ah[1] = *(const u32*)(qp + 8 * KQS);
            ah[2] = *(const u32*)(qp + 8);
            ah[3] = *(const u32*)(qp + 8 * KQS + 8);
            al4[0] = *(const u32*)qlp;
            al4[1] = *(const u32*)(qlp + 8 * KQS);
            al4[2] = *(const u32*)(qlp + 8);
            al4[3] = *(const u32*)(qlp + 8 * KQS + 8);
            u32 bh_[2][2], bl_[2][2];
#pragma unroll
            for (int n = 0; n < 2; ++n) {
                const bf16* kp = Kh + (jg + n * 8 + g) * KQS + ko;
                const bf16* klp = Kl + (jg + n * 8 + g) * KQS + ko;
                bh_[n][0] = *(const u32*)kp;
                bh_[n][1] = *(const u32*)(kp + 8);
                bl_[n][0] = *(const u32*)klp;
                bl_[n][1] = *(const u32*)(klp + 8);
            }
#pragma unroll
            for (int n = 0; n < 2; ++n) mma16816(acc[n], ah, bh_[n]);
#pragma unroll
            for (int n = 0; n < 2; ++n) mma16816(acc[n], ah, bl_[n]);
#pragma unroll
            for (int n = 0; n < 2; ++n) mma16816(acc[n], al4, bh_[n]);
        }

        const int jb0 = jc * 128 + jg;
#pragma unroll
        for (int n = 0; n < 2; ++n) {
#pragma unroll
            for (int hh = 0; hh < 2; ++hh) {
                const int il = m0 + g + 8 * hh;
                const int gi = i0 + il;
                const int jj = jb0 + n * 8 + 2 * tg;
                const float* brow = biasW + il * 132;
                int r0 = min(max(jj - gi, -MREL), MREL) + MREL;
                int r1 = min(max(jj + 1 - gi, -MREL), MREL) + MREL;
                float2 o;
                o.x = acc[n][2 * hh] * 0.125f + brow[r0];
                o.y = acc[n][2 * hh + 1] * 0.125f + brow[r1];
                *(float2*)&Sb[il * SBS + jj] = o;
            }
        }
        __syncthreads();
    }

    // ================= PHASE 2: softmax + raw wsum (16 lanes/row) =========
    {
        const int row = tid >> 4;
        const int ts = tid & 15;
        const int gi = i0 + row;
        float* srow = Sb + row * SBS;

        float m = -3.0e38f;
#pragma unroll 16
        for (int c = 0; c < 16; ++c) {
            float4 v = *(const float4*)&srow[ts * 4 + c * 64];
            m = fmaxf(m, fmaxf(fmaxf(v.x, v.y), fmaxf(v.z, v.w)));
        }
#pragma unroll
        for (int o = 8; o > 0; o >>= 1)
            m = fmaxf(m, __shfl_xor_sync(0xffffffffu, m, o));

        float s = 0.0f;
#pragma unroll 16
        for (int c = 0; c < 16; ++c) {
            float4 v = *(float4*)&srow[ts * 4 + c * 64];
            v.x = __expf(v.x - m); v.y = __expf(v.y - m);
            v.z = __expf(v.z - m); v.w = __expf(v.w - m);
            *(float4*)&srow[ts * 4 + c * 64] = v;
            s += v.x + v.y + v.z + v.w;
        }
#pragma unroll
        for (int o = 8; o > 0; o >>= 1) s += __shfl_xor_sync(0xffffffffu, s, o);
        if (ts == 0) invS[row] = 1.0f / s;

        float hp = 0.0f, tp = 0.0f;
        for (int j = ts; j <= gi - MREL; j += 16) hp += srow[j];
        for (int j = gi + MREL + ts; j < L; j += 16) tp += srow[j];
#pragma unroll
        for (int o = 8; o > 0; o >>= 1) {
            hp += __shfl_xor_sync(0xffffffffu, hp, o);
            tp += __shfl_xor_sync(0xffffffffu, tp, o);
        }
        __syncthreads();

        float* wrow = biasW + row * 132;
#pragma unroll
        for (int k = 0; k < 8; ++k) {
            int r = 1 + ts * 8 + k;
            if (r < 128) {
                int j = gi + r - 64;
                wrow[r] = (j >= 0 && j < L) ? srow[j] : 0.0f;
            }
        }
        if (ts == 0) {
            wrow[0] = hp;
            wrow[128] = tp;
        }
    }

    // ================= PHASE 3: O = exp @ V via mma (warp tile 16x8) ======
    const int dd = tid >> 3, js = (tid & 7) * 16;
    const bf16* vhg = g_vth + ((size_t)bh * 64 + dd) * 1024 + js;
    const bf16* vlg = g_vtl + ((size_t)bh * 64 + dd) * 1024 + js;
    uint4 vph[2], vpl[2];
#pragma unroll
    for (int u = 0; u < 2; ++u) {
        vph[u] = *(const uint4*)(vhg + 8 * u);
        vpl[u] = *(const uint4*)(vlg + 8 * u);
    }
    __syncthreads();

    float acc3[4];
#pragma unroll
    for (int e = 0; e < 4; ++e) acc3[e] = 0.0f;
    const int dg = (w >> 1) * 8;            // 8 d-groups of 8

    for (int jc = 0; jc < 8; ++jc) {
#pragma unroll
        for (int u = 0; u < 2; ++u) {
            *(uint4*)(Vh + dd * WVS + js + 8 * u) = vph[u];
            *(uint4*)(Vl + dd * WVS + js + 8 * u) = vpl[u];
        }
        {
            const int rr = tid & 31, cs = (tid >> 5) * 8;   // 16 groups x 8
            const float* sp = Sb + rr * SBS + jc * 128 + cs;
            float4 x0 = ((const float4*)sp)[0];
            float4 x1 = ((const float4*)sp)[1];
            *(uint4*)(Wh + rr * WVS + cs) = make_uint4(
                pkh2(x0.x, x0.y), pkh2(x0.z, x0.w), pkh2(x1.x, x1.y), pkh2(x1.z, x1.w));
            *(uint4*)(Wl + rr * WVS + cs) = make_uint4(
                pkl2(x0.x, x0.y), pkl2(x0.z, x0.w), pkl2(x1.x, x1.y), pkl2(x1.z, x1.w));
        }
        __syncthreads();
        if (jc < 7) {
            const int jn = (jc + 1) * 128;
#pragma unroll
            for (int u = 0; u < 2; ++u) {
                vph[u] = *(const uint4*)(vhg + jn + 8 * u);
                vpl[u] = *(const uint4*)(vlg + jn + 8 * u);
            }
        }

#pragma unroll
        for (int kk = 0; kk < 8; ++kk) {
            const int ko = kk * 16 + 2 * tg;
            const bf16* wp = Wh + (m0 + g) * WVS + ko;
            const bf16* wlp = Wl + (m0 + g) * WVS + ko;
            u32 ah[4], al4[4];
            ah[0] = *(const u32*)wp;
            ah[1] = *(const u32*)(wp + 8 * WVS);
            ah[2] = *(const u32*)(wp + 8);
            ah[3] = *(const u32*)(wp + 8 * WVS + 8);
            al4[0] = *(const u32*)wlp;
            al4[1] = *(const u32*)(wlp + 8 * WVS);
            al4[2] = *(const u32*)(wlp + 8);
            al4[3] = *(const u32*)(wlp + 8 * WVS + 8);
            u32 bh_[2], bl_[2];
            const bf16* vp = Vh + (dg + g) * WVS + ko;
            const bf16* vlp = Vl + (dg + g) * WVS + ko;
            bh_[0] = *(const u32*)vp;
            bh_[1] = *(const u32*)(vp + 8);
            bl_[0] = *(const u32*)vlp;
            bl_[1] = *(const u32*)(vlp + 8);
            mma16816(acc3, ah, bh_);
            mma16816(acc3, ah, bl_);
            mma16816(acc3, al4, bh_);
        }
        __syncthreads();
    }

    // write O accumulators to smem; stage relv
#pragma unroll
    for (int hh = 0; hh < 2; ++hh) {
        const int il = m0 + g + 8 * hh;
        *(float2*)&Osm[il * 68 + dg + 2 * tg] =
            make_float2(acc3[2 * hh], acc3[2 * hh + 1]);
    }
    for (int e = tid; e < R * 64; e += 512) {
        relvS[(e >> 6) * 68 + (e & 63)] = relv[e];
    }
    __syncthreads();

    // ================= PHASE 4: rel_v + writeout (bf16 hi/lo) =============
    {
        const int ii = tid & 31, dgp = (tid >> 5) * 4;   // 16 groups x 4 d
        const float* wrow = biasW + ii * 132;
        u64 a4[2] = {0ull, 0ull};
        for (int r = 0; r <= 128; ++r) {
            u64 wd = dup2(wrow[r]);
            const float* vr = relvS + r * 68 + dgp;
            a4[0] = ffma2(wd, *(const u64*)(vr + 0), a4[0]);
            a4[1] = ffma2(wd, *(const u64*)(vr + 2), a4[1]);
        }
        const float iv = invS[ii];
        const float* op = Osm + ii * 68 + dgp;
        float2 p0 = up2(a4[0]), p1 = up2(a4[1]);
        float o0 = (op[0] + p0.x) * iv, o1 = (op[1] + p0.y) * iv;
        float o2 = (op[2] + p1.x) * iv, o3 = (op[3] + p1.y) * iv;
        const size_t ob = (size_t)(b * L + i0 + ii) * D + h * DH + dgp;
        *(uint2*)(g_xh + ob) = make_uint2(pkh2(o0, o1), pkh2(o2, o3));
        *(uint2*)(g_xl + ob) = make_uint2(pkl2(o0, o1), pkl2(o2, o3));
    }
}

// ---------------------------------------------------------------------------
// Launch
// ---------------------------------------------------------------------------
extern "C" void kernel_launch(void* const* d_in, const int* in_sizes, int n_in,
                              void* d_out, int out_size) {
    const float* x    = (const float*)d_in[0];
    const float* Wq   = (const float*)d_in[1];
    const float* Wk   = (const float*)d_in[2];
    const float* Wv   = (const float*)d_in[3];
    const float* Wo   = (const float*)d_in[4];
    const float* relk = (const float*)d_in[5];
    const float* relv = (const float*)d_in[6];
    float* out = (float*)d_out;

    float* pqkv;
    cudaGetSymbolAddress((void**)&pqkv, g_qkv);
    bf16 *xh, *xl, *wh3, *wl3, *woh, *wol, *vth, *vtl;
    cudaGetSymbolAddress((void**)&xh, g_xh);
    cudaGetSymbolAddress((void**)&xl, g_xl);
    cudaGetSymbolAddress((void**)&wh3, g_wh3);
    cudaGetSymbolAddress((void**)&wl3, g_wl3);
    cudaGetSymbolAddress((void**)&woh, g_woh);
    cudaGetSymbolAddress((void**)&wol, g_wol);
    cudaGetSymbolAddress((void**)&vth, g_vth);
    cudaGetSymbolAddress((void**)&vtl, g_vtl);

    cudaFuncSetAttribute(mega_attn_kernel,
                         cudaFuncAttributeMaxDynamicSharedMemorySize,
                         (int)MEGA_SMEM);
    cudaFuncSetAttribute(hgemm3x,
                         cudaFuncAttributeMaxDynamicSharedMemorySize,
                         (int)HG_SMEM);

    const dim3 gqkv(QKV / 128, NT / 128);   // (24, 16)
    const dim3 gout(D / 128, NT / 128);     // (8, 16)
    const dim3 gt(32, 32);
    const dim3 gt3(32, 32, 3);
    const dim3 gvt(L / 32, 2, BH);          // (32, 2, 32)
    const dim3 bt(32, 8);
    const int splitBlocks = (NT * D) / (256 * 4);
    const int ksplitBlocks = (BH * 1024 * 64) / (256 * 4);   // 2048

    split_kernel<<<splitBlocks, 256>>>(x, xh, xl);
    splitT3_kernel<<<gt3, bt>>>(Wq, Wk, Wv, wh3, wl3);
    splitT_kernel<<<gt, bt>>>(Wo, woh, wol);
    hgemm3x<<<gqkv, 256, HG_SMEM>>>(xh, xl, wh3, wl3, pqkv, NT, QKV, D);
    ksplit_kernel<<<ksplitBlocks, 256>>>();
    vt_kernel<<<gvt, bt>>>(vth, vtl);
    relq_kernel<<<dim3(L / 32, BH), 256>>>(relk);
    mega_attn_kernel<<<dim3(L / 32, BH), 512, MEGA_SMEM>>>(relv);
    hgemm3x<<<gout, 256, HG_SMEM>>>(xh, xl, woh, wol, out, NT, D, D);
}